// round 8
// baseline (speedup 1.0000x reference)
#include <cuda_runtime.h>
#include <cuda_bf16.h>
#include <cstdint>

// Problem constants
constexpr int HID = 1024;
constexpr int NH  = 16;
constexpr int HD  = 64;
constexpr int B   = 2;
constexpr int S   = 2048;
constexpr int M   = B * S;

// ---------------------------------------------------------------------------
// Scratch (__device__ globals; allocation-free rule)
// ---------------------------------------------------------------------------
__device__ __nv_bfloat16 g_xhi[(size_t)M * HID];
__device__ __nv_bfloat16 g_xlo[(size_t)M * HID];
__device__ __nv_bfloat16 g_whi[(size_t)4 * HID * HID];   // [Wq|Wk|Wv|Wo]
__device__ __nv_bfloat16 g_wlo[(size_t)4 * HID * HID];
__device__ __nv_bfloat16 g_qhi[(size_t)M * HID];         // [B,H,S,D], q *0.125
__device__ __nv_bfloat16 g_qlo[(size_t)M * HID];
__device__ __nv_bfloat16 g_khi[(size_t)M * HID];
__device__ __nv_bfloat16 g_klo[(size_t)M * HID];
__device__ __nv_bfloat16 g_vhi[(size_t)M * HID];
__device__ __nv_bfloat16 g_vlo[(size_t)M * HID];
__device__ __nv_bfloat16 g_ahi[(size_t)M * HID];         // attn out [B,S,HID]
__device__ __nv_bfloat16 g_alo[(size_t)M * HID];

// ---------------------------------------------------------------------------
// PTX helpers
// ---------------------------------------------------------------------------
__device__ __forceinline__ uint32_t smem_u32(const void* p) {
    uint32_t a;
    asm("{ .reg .u64 t; cvta.to.shared.u64 t, %1; cvt.u32.u64 %0, t; }"
        : "=r"(a) : "l"(p));
    return a;
}

__device__ __forceinline__ void ldsm_x4(uint32_t (&r)[4], uint32_t addr) {
    asm volatile("ldmatrix.sync.aligned.m8n8.x4.shared.b16 {%0,%1,%2,%3}, [%4];"
                 : "=r"(r[0]), "=r"(r[1]), "=r"(r[2]), "=r"(r[3]) : "r"(addr));
}

__device__ __forceinline__ void ldsm_x4_t(uint32_t (&r)[4], uint32_t addr) {
    asm volatile("ldmatrix.sync.aligned.m8n8.x4.trans.shared.b16 {%0,%1,%2,%3}, [%4];"
                 : "=r"(r[0]), "=r"(r[1]), "=r"(r[2]), "=r"(r[3]) : "r"(addr));
}

__device__ __forceinline__ void mma_bf16(float (&d)[4], const uint32_t (&a)[4],
                                         uint32_t b0, uint32_t b1) {
    asm volatile(
        "mma.sync.aligned.m16n8k16.row.col.f32.bf16.bf16.f32 "
        "{%0,%1,%2,%3}, {%4,%5,%6,%7}, {%8,%9}, {%0,%1,%2,%3};"
        : "+f"(d[0]), "+f"(d[1]), "+f"(d[2]), "+f"(d[3])
        : "r"(a[0]), "r"(a[1]), "r"(a[2]), "r"(a[3]), "r"(b0), "r"(b1));
}

__device__ __forceinline__ void cp16(uint32_t dst, const void* src) {
    asm volatile("cp.async.cg.shared.global [%0], [%1], 16;"
                 :: "r"(dst), "l"(src));
}
#define CP_COMMIT() asm volatile("cp.async.commit_group;")
#define CP_WAIT(n)  asm volatile("cp.async.wait_group %0;" :: "n"(n))
#define BAR64(id)   asm volatile("bar.sync %0, 64;" :: "r"(id))

__device__ __forceinline__ uint32_t pack2bf16(float a, float b) {
    __nv_bfloat162 h = __floats2bfloat162_rn(a, b);
    return *reinterpret_cast<uint32_t*>(&h);
}
__device__ __forceinline__ float bf16round(float x) {
    return __bfloat162float(__float2bfloat16(x));
}

// ---------------------------------------------------------------------------
// Pre-pass: split f32 -> bf16 (hi, lo).  sel: 0 = x, 1..4 = W[sel-1]
// ---------------------------------------------------------------------------
__global__ __launch_bounds__(256)
void cvt_kernel(const float* __restrict__ src, int sel)
{
    __nv_bfloat16 *hi, *lo;
    if (sel == 0) { hi = g_xhi; lo = g_xlo; }
    else {
        hi = g_whi + (size_t)(sel - 1) * HID * HID;
        lo = g_wlo + (size_t)(sel - 1) * HID * HID;
    }
    const int i = blockIdx.x * 256 + threadIdx.x;
    float4 v = ((const float4*)src)[i];
    const float hx = bf16round(v.x), hy = bf16round(v.y);
    const float hz = bf16round(v.z), hw = bf16round(v.w);
    ((uint2*)hi)[i] = make_uint2(pack2bf16(v.x, v.y), pack2bf16(v.z, v.w));
    ((uint2*)lo)[i] = make_uint2(pack2bf16(v.x - hx, v.y - hy),
                                 pack2bf16(v.z - hz, v.w - hw));
}

// ---------------------------------------------------------------------------
// GEMM: 512 threads, 16 warps (4x4 grid, 32x32 warp tile), BK=32, 3-stage
// cp.async pipeline. IS_O=0: fused QKV (n over 3072) -> scatter hi/lo
// [B,H,S,D]. IS_O=1: O-projection -> f32 out.
// ---------------------------------------------------------------------------
constexpr int G_TILE  = 128 * 80;      // 10240 B (128 rows x 80B)
constexpr int G_STAGE = 4 * G_TILE;    // 40960 B
constexpr int G_SMEM  = 3 * G_STAGE;   // 122880 B

template <int IS_O>
__global__ __launch_bounds__(512)
void gemm_mma_kernel(const float* __restrict__ bq_,
                     const float* __restrict__ bk_,
                     const float* __restrict__ bv_,
                     float* __restrict__ Cout)
{
    extern __shared__ char dynsm[];
    const uint32_t smb = smem_u32(dynsm);

    const __nv_bfloat16* Ahi_g = IS_O ? g_ahi : g_xhi;
    const __nv_bfloat16* Alo_g = IS_O ? g_alo : g_xlo;
    const __nv_bfloat16* Whi_g = g_whi + (IS_O ? (size_t)3 * HID * HID : 0);
    const __nv_bfloat16* Wlo_g = g_wlo + (IS_O ? (size_t)3 * HID * HID : 0);

    const int t      = threadIdx.x;
    const int lane   = t & 31;
    const int wid    = t >> 5;
    const int warp_m = wid >> 2;     // 0..3 -> 32 rows
    const int warp_n = wid & 3;      // 0..3 -> 32 cols
    const int m0 = blockIdx.y * 128;
    const int n0 = blockIdx.x * 128;

    const int a_row = lane & 15;
    const int a_kb  = (lane >> 4) * 16;
    const int b_row = (lane & 7) + ((lane >> 4) << 3);
    const int b_kb  = ((lane >> 3) & 1) * 16;

    const int lr = t >> 2;           // 0..127
    const int lj = t & 3;            // 0..3

    auto load_chunk = [&](int stage, int k0) {
        const size_t aoff = (size_t)(m0 + lr) * HID + k0 + lj * 8;
        const size_t woff = (size_t)(n0 + lr) * HID + k0 + lj * 8;
        const uint32_t d = smb + stage * G_STAGE + lr * 80 + lj * 16;
        cp16(d,              Ahi_g + aoff);
        cp16(d + G_TILE,     Alo_g + aoff);
        cp16(d + 2 * G_TILE, Whi_g + woff);
        cp16(d + 3 * G_TILE, Wlo_g + woff);
    };

    float acc[2][4][4];
#pragma unroll
    for (int mt = 0; mt < 2; mt++)
#pragma unroll
        for (int nt = 0; nt < 4; nt++)
#pragma unroll
            for (int r = 0; r < 4; r++) acc[mt][nt][r] = 0.f;

    load_chunk(0, 0);  CP_COMMIT();
    load_chunk(1, 32); CP_COMMIT();

    for (int c = 0; c < 32; c++) {
        if (c + 2 < 32) { load_chunk((c + 2) % 3, (c + 2) * 32); CP_COMMIT(); CP_WAIT(2); }
        else if (c + 1 < 32) { CP_WAIT(1); }
        else { CP_WAIT(0); }
        __syncthreads();

        const uint32_t sb = smb + (c % 3) * G_STAGE;
#pragma unroll
        for (int ks = 0; ks < 2; ks++) {
            const int ksb = ks * 32;

            uint32_t a_hi[2][4], a_lo[2][4];
#pragma unroll
            for (int mt = 0; mt < 2; mt++) {
                const uint32_t ro =
                    (uint32_t)((warp_m * 32 + mt * 16 + a_row) * 80 + ksb + a_kb);
                ldsm_x4(a_hi[mt], sb + ro);
                ldsm_x4(a_lo[mt], sb + G_TILE + ro);
            }
            uint32_t b_hi[2][4], b_lo[2][4];
#pragma unroll
            for (int bt = 0; bt < 2; bt++) {
                const uint32_t ro =
                    (uint32_t)((warp_n * 32 + bt * 16 + b_row) * 80 + ksb + b_kb);
                ldsm_x4(b_hi[bt], sb + 2 * G_TILE + ro);
                ldsm_x4(b_lo[bt], sb + 3 * G_TILE + ro);
            }

#pragma unroll
            for (int mt = 0; mt < 2; mt++)
#pragma unroll
                for (int nt = 0; nt < 4; nt++) {
                    const int bt = nt >> 1;
                    const int hf = (nt & 1) * 2;
                    mma_bf16(acc[mt][nt], a_hi[mt], b_hi[bt][hf], b_hi[bt][hf + 1]);
                    mma_bf16(acc[mt][nt], a_hi[mt], b_lo[bt][hf], b_lo[bt][hf + 1]);
                    mma_bf16(acc[mt][nt], a_lo[mt], b_hi[bt][hf], b_hi[bt][hf + 1]);
                }
        }
        __syncthreads();
    }

    // ---- epilogue ----
    const int fr = lane >> 2;
    const int fc = (lane & 3) * 2;
#pragma unroll
    for (int mt = 0; mt < 2; mt++)
#pragma unroll
        for (int nt = 0; nt < 4; nt++) {
            const int n_g = n0 + warp_n * 32 + nt * 8 + fc;
            float2 b2;
            float scl = 1.f;
            int w_idx = 0, n_w = n_g;
            if (!IS_O) {
                w_idx = n_g >> 10;
                n_w   = n_g & 1023;
                const float* bias = (w_idx == 0) ? bq_ : (w_idx == 1) ? bk_ : bv_;
                b2 = *(const float2*)&bias[n_w];
                if (w_idx == 0) scl = 0.125f;
            } else {
                b2 = *(const float2*)&bq_[n_g];
            }
#pragma unroll
            for (int p = 0; p < 2; p++) {
                const int m = m0 + warp_m * 32 + mt * 16 + fr + p * 8;
                const float vx = (acc[mt][nt][p * 2 + 0] + b2.x) * scl;
                const float vy = (acc[mt][nt][p * 2 + 1] + b2.y) * scl;
                if (!IS_O) {
                    const int bb = m >> 11;
                    const int ss = m & (S - 1);
                    const int hh = n_w >> 6;
                    const int dd = n_w & 63;
                    const size_t idx =
                        (((size_t)(bb * NH + hh) * S + ss) << 6) + dd;
                    __nv_bfloat16* Chi = (w_idx == 0) ? g_qhi
                                       : (w_idx == 1) ? g_khi : g_vhi;
                    __nv_bfloat16* Clo = (w_idx == 0) ? g_qlo
                                       : (w_idx == 1) ? g_klo : g_vlo;
                    *(uint32_t*)&Chi[idx] = pack2bf16(vx, vy);
                    *(uint32_t*)&Clo[idx] =
                        pack2bf16(vx - bf16round(vx), vy - bf16round(vy));
                } else {
                    float2 v; v.x = vx; v.y = vy;
                    *(float2*)&Cout[(size_t)m * HID + n_g] = v;
                }
            }
        }
}

// ---------------------------------------------------------------------------
// Attention: 512 threads, 16 warps. 128 q-rows/CTA; 64-key tiles split
// across warp pairs (warp_c in {0,1}: 32 keys each). Q persistent in smem.
// Softmax combined across pairs via named barriers; partial O summed at end.
// ---------------------------------------------------------------------------
constexpr int KST     = 72;                 // bf16 row stride (144 B)
constexpr int A_TILE  = 64 * KST * 2;       // 9216 B
constexpr int A_STAGE = 4 * A_TILE;         // 36864 B (Khi|Klo|Vhi|Vlo)
constexpr int A_QREG  = 128 * KST * 2;      // 18432 B per Q array
constexpr int A_SMEM  = 2 * A_STAGE + 2 * A_QREG;   // 110592 B

__global__ __launch_bounds__(512)
void attn_mma_kernel()
{
    extern __shared__ char dynsm[];
    const uint32_t smb = smem_u32(dynsm);
    __shared__ float redM[8][2][16];
    __shared__ float redS[8][2][16];

    const int t      = threadIdx.x;
    const int lane   = t & 31;
    const int w      = t >> 5;
    const int warp_r = w & 7;       // q-row group (16 rows)
    const int warp_c = w >> 3;      // key half (32 keys)
    const int q0     = (gridDim.x - 1 - blockIdx.x) * 128;
    const int bh     = blockIdx.y;
    const int bb     = bh >> 4;
    const int hh     = bh & 15;

    const size_t bh_off = (size_t)bh * S * HD;
    const __nv_bfloat16* Khi_g = g_khi + bh_off;
    const __nv_bfloat16* Klo_g = g_klo + bh_off;
    const __nv_bfloat16* Vhi_g = g_vhi + bh_off;
    const __nv_bfloat16* Vlo_g = g_vlo + bh_off;

    const uint32_t qhi_b = smb + 2 * A_STAGE;
    const uint32_t qlo_b = qhi_b + A_QREG;

    // ---- stage Q (persistent) ----
#pragma unroll
    for (int it = 0; it < 2; it++) {
        const int i = t + it * 512;     // 0..1023
        const int r = i >> 3;
        const int j = i & 7;
        const size_t off = bh_off + (size_t)(q0 + r) * HD + j * 8;
        cp16(qhi_b + r * 144 + j * 16, g_qhi + off);
        cp16(qlo_b + r * 144 + j * 16, g_qlo + off);
    }
    CP_COMMIT();

    const int a_row = lane & 15;
    const int a_kb  = (lane >> 4) * 16;
    const int b_row = (lane & 7) + ((lane >> 4) << 3);
    const int b_kb  = ((lane >> 3) & 1) * 16;

    // tile loader: 512 chunks per array -> 1 per thread
    const int tr = t >> 3, tj = t & 7;
    auto load_tile = [&](int stage, int k0) {
        const size_t off = (size_t)(k0 + tr) * HD + tj * 8;
        const uint32_t d = smb + stage * A_STAGE + tr * 144 + tj * 16;
        cp16(d,              Khi_g + off);
        cp16(d + A_TILE,     Klo_g + off);
        cp16(d + 2 * A_TILE, Vhi_g + off);
        cp16(d + 3 * A_TILE, Vlo_g + off);
    };

    float m0 = -1e30f, m1 = -1e30f, l0 = 0.f, l1 = 0.f;
    float oacc[8][4];
#pragma unroll
    for (int nt = 0; nt < 8; nt++)
#pragma unroll
        for (int r = 0; r < 4; r++) oacc[nt][r] = 0.f;

    const int nk = q0 / 64 + 2;
    load_tile(0, 0);
    CP_COMMIT();

    for (int ki = 0; ki < nk; ki++) {
        const int k0 = ki * 64;
        if (ki + 1 < nk) { load_tile((ki + 1) & 1, k0 + 64); CP_COMMIT(); CP_WAIT(1); }
        else             { CP_WAIT(0); }
        __syncthreads();

        const uint32_t sb = smb + (ki & 1) * A_STAGE;

        // ---- S = Q @ K^T (warp's 32 keys; 3-term split) ----
        float sacc[4][4];
#pragma unroll
        for (int nt = 0; nt < 4; nt++)
#pragma unroll
            for (int r = 0; r < 4; r++) sacc[nt][r] = 0.f;

#pragma unroll
        for (int ks = 0; ks < 4; ks++) {
            uint32_t qh[4], ql[4];
            const uint32_t roq =
                (uint32_t)((warp_r * 16 + a_row) * 144 + ks * 32 + a_kb);
            ldsm_x4(qh, qhi_b + roq);
            ldsm_x4(ql, qlo_b + roq);

            uint32_t kh[2][4], kl[2][4];
#pragma unroll
            for (int g = 0; g < 2; g++) {
                const uint32_t ro =
                    (uint32_t)((warp_c * 32 + g * 16 + b_row) * 144 + ks * 32 + b_kb);
                ldsm_x4(kh[g], sb + ro);
                ldsm_x4(kl[g], sb + A_TILE + ro);
            }
#pragma unroll
            for (int nt = 0; nt < 4; nt++) {
                const int g  = nt >> 1;
                const int hf = (nt & 1) * 2;
                mma_bf16(sacc[nt], qh, kh[g][hf], kh[g][hf + 1]);
                mma_bf16(sacc[nt], qh, kl[g][hf], kl[g][hf + 1]);
                mma_bf16(sacc[nt], ql, kh[g][hf], kh[g][hf + 1]);
            }
        }

        // ---- causal mask ----
        if (k0 >= q0) {
            const int grow = q0 + warp_r * 16 + (lane >> 2);
#pragma unroll
            for (int nt = 0; nt < 4; nt++) {
                const int gc = k0 + warp_c * 32 + nt * 8 + (lane & 3) * 2;
                if (gc     > grow)     sacc[nt][0] = -1e30f;
                if (gc + 1 > grow)     sacc[nt][1] = -1e30f;
                if (gc     > grow + 8) sacc[nt][2] = -1e30f;
                if (gc + 1 > grow + 8) sacc[nt][3] = -1e30f;
            }
        }

        // ---- softmax: intra-warp then cross-pair combine ----
        float mx0 = -1e30f, mx1 = -1e30f;
#pragma unroll
        for (int nt = 0; nt < 4; nt++) {
            mx0 = fmaxf(mx0, fmaxf(sacc[nt][0], sacc[nt][1]));
            mx1 = fmaxf(mx1, fmaxf(sacc[nt][2], sacc[nt][3]));
        }
        mx0 = fmaxf(mx0, __shfl_xor_sync(0xffffffffu, mx0, 1));
        mx0 = fmaxf(mx0, __shfl_xor_sync(0xffffffffu, mx0, 2));
        mx1 = fmaxf(mx1, __shfl_xor_sync(0xffffffffu, mx1, 1));
        mx1 = fmaxf(mx1, __shfl_xor_sync(0xffffffffu, mx1, 2));

        if ((lane & 3) == 0) {
            redM[warp_r][warp_c][lane >> 2]       = mx0;
            redM[warp_r][warp_c][8 + (lane >> 2)] = mx1;
        }
        BAR64(1 + warp_r);
        mx0 = fmaxf(mx0, redM[warp_r][warp_c ^ 1][lane >> 2]);
        mx1 = fmaxf(mx1, redM[warp_r][warp_c ^ 1][8 + (lane >> 2)]);

        const float mn0 = fmaxf(m0, mx0);
        const float mn1 = fmaxf(m1, mx1);
        float sum0 = 0.f, sum1 = 0.f;
#pragma unroll
        for (int nt = 0; nt < 4; nt++) {
            sacc[nt][0] = __expf(sacc[nt][0] - mn0); sum0 += sacc[nt][0];
            sacc[nt][1] = __expf(sacc[nt][1] - mn0); sum0 += sacc[nt][1];
            sacc[nt][2] = __expf(sacc[nt][2] - mn1); sum1 += sacc[nt][2];
            sacc[nt][3] = __expf(sacc[nt][3] - mn1); sum1 += sacc[nt][3];
        }
        sum0 += __shfl_xor_sync(0xffffffffu, sum0, 1);
        sum0 += __shfl_xor_sync(0xffffffffu, sum0, 2);
        sum1 += __shfl_xor_sync(0xffffffffu, sum1, 1);
        sum1 += __shfl_xor_sync(0xffffffffu, sum1, 2);

        if ((lane & 3) == 0) {
            redS[warp_r][warp_c][lane >> 2]       = sum0;
            redS[warp_r][warp_c][8 + (lane >> 2)] = sum1;
        }
        BAR64(1 + warp_r);
        sum0 += redS[warp_r][warp_c ^ 1][lane >> 2];
        sum1 += redS[warp_r][warp_c ^ 1][8 + (lane >> 2)];

        const float sc0 = __expf(m0 - mn0);
        const float sc1 = __expf(m1 - mn1);
        l0 = l0 * sc0 + sum0; m0 = mn0;
        l1 = l1 * sc1 + sum1; m1 = mn1;
#pragma unroll
        for (int nt = 0; nt < 8; nt++) {
            oacc[nt][0] *= sc0; oacc[nt][1] *= sc0;
            oacc[nt][2] *= sc1; oacc[nt][3] *= sc1;
        }

        // ---- O += P @ V  (warp's 32 keys; V rows warp_c*32..) ----
#pragma unroll
        for (int ks2 = 0; ks2 < 2; ks2++) {
            uint32_t ph[4], pl[4];
            {
                const float p00 = sacc[2 * ks2][0],     p01 = sacc[2 * ks2][1];
                const float p02 = sacc[2 * ks2][2],     p03 = sacc[2 * ks2][3];
                const float p10 = sacc[2 * ks2 + 1][0], p11 = sacc[2 * ks2 + 1][1];
                const float p12 = sacc[2 * ks2 + 1][2], p13 = sacc[2 * ks2 + 1][3];
                ph[0] = pack2bf16(p00, p01);
                ph[1] = pack2bf16(p02, p03);
                ph[2] = pack2bf16(p10, p11);
                ph[3] = pack2bf16(p12, p13);
                pl[0] = pack2bf16(p00 - bf16round(p00), p01 - bf16round(p01));
                pl[1] = pack2bf16(p02 - bf16round(p02), p03 - bf16round(p03));
                pl[2] = pack2bf16(p10 - bf16round(p10), p11 - bf16round(p11));
                pl[3] = pack2bf16(p12 - bf16round(p12), p13 - bf16round(p13));
            }
            uint32_t vh[4][4], vl[4][4];
#pragma unroll
            for (int g = 0; g < 4; g++) {
                const uint32_t ro =
                    (uint32_t)((warp_c * 32 + ks2 * 16 + a_row) * 144 + g * 32 + a_kb);
                ldsm_x4_t(vh[g], sb + 2 * A_TILE + ro);
                ldsm_x4_t(vl[g], sb + 3 * A_TILE + ro);
            }
#pragma unroll
            for (int nt = 0; nt < 8; nt++) {
                const int g  = nt >> 1;
                const int hf = (nt & 1) * 2;
                mma_bf16(oacc[nt], ph, vh[g][hf], vh[g][hf + 1]);
                mma_bf16(oacc[nt], ph, vl[g][hf], vl[g][hf + 1]);
                mma_bf16(oacc[nt], pl, vh[g][hf], vh[g][hf + 1]);
            }
        }
        __syncthreads();
    }

    // ---- combine partial O across warp pairs via smem ----
    float* scr = (float*)dynsm;   // reuse tile stages (safe: sync above)
#pragma unroll
    for (int j = 0; j < 4; j++) {
        const int nt = warp_c ? j : 4 + j;   // write the half we give away
        float4 v;
        v.x = oacc[nt][0]; v.y = oacc[nt][1];
        v.z = oacc[nt][2]; v.w = oacc[nt][3];
        *(float4*)&scr[((warp_r * 2 + warp_c) * 4 + j) * 128 + lane * 4] = v;
    }
    __syncthreads();
#pragma unroll
    for (int j = 0; j < 4; j++) {
        const int nt = warp_c ? 4 + j : j;   // the half we keep
        const float4 v =
            *(const float4*)&scr[((warp_r * 2 + (warp_c ^ 1)) * 4 + j) * 128 + lane * 4];
        oacc[nt][0] += v.x; oacc[nt][1] += v.y;
        oacc[nt][2] += v.z; oacc[nt][3] += v.w;
    }

    // ---- finalize + write bf16 hi/lo (warp outputs its 32 d-cols) ----
    const float il0 = 1.f / l0;
    const float il1 = 1.f / l1;
    const int r0 = q0 + warp_r * 16 + (lane >> 2);
#pragma unroll
    for (int j = 0; j < 4; j++) {
        const int nt = warp_c ? 4 + j : j;
        const int d  = warp_c * 32 + j * 8 + (lane & 3) * 2;
        const float v0x = oacc[nt][0] * il0, v0y = oacc[nt][1] * il0;
        const float v1x = oacc[nt][2] * il1, v1y = oacc[nt][3] * il1;
        const size_t i0 = ((size_t)bb * S + r0) * HID + hh * 64 + d;
        const size_t i1 = ((size_t)bb * S + r0 + 8) * HID + hh * 64 + d;
        *(uint32_t*)&g_ahi[i0] = pack2bf16(v0x, v0y);
        *(uint32_t*)&g_alo[i0] =
            pack2bf16(v0x - bf16round(v0x), v0y - bf16round(v0y));
        *(uint32_t*)&g_ahi[i1] = pack2bf16(v1x, v1y);
        *(uint32_t*)&g_alo[i1] =
            pack2bf16(v1x - bf16round(v1x), v1y - bf16round(v1y));
    }
}

// ---------------------------------------------------------------------------
// Launch
// ---------------------------------------------------------------------------
extern "C" void kernel_launch(void* const* d_in, const int* in_sizes, int n_in,
                              void* d_out, int out_size)
{
    const float* x  = (const float*)d_in[0];
    const float* Wq = (const float*)d_in[1];
    const float* bq = (const float*)d_in[2];
    const float* Wk = (const float*)d_in[3];
    const float* bk = (const float*)d_in[4];
    const float* Wv = (const float*)d_in[5];
    const float* bv = (const float*)d_in[6];
    const float* Wo = (const float*)d_in[7];
    const float* bo = (const float*)d_in[8];
    float* out = (float*)d_out;

    cudaFuncSetAttribute(attn_mma_kernel,
                         cudaFuncAttributeMaxDynamicSharedMemorySize, A_SMEM);
    cudaFuncSetAttribute(gemm_mma_kernel<0>,
                         cudaFuncAttributeMaxDynamicSharedMemorySize, G_SMEM);
    cudaFuncSetAttribute(gemm_mma_kernel<1>,
                         cudaFuncAttributeMaxDynamicSharedMemorySize, G_SMEM);

    cvt_kernel<<<(M * HID / 4) / 256, 256>>>(x, 0);
    cvt_kernel<<<(HID * HID / 4) / 256, 256>>>(Wq, 1);
    cvt_kernel<<<(HID * HID / 4) / 256, 256>>>(Wk, 2);
    cvt_kernel<<<(HID * HID / 4) / 256, 256>>>(Wv, 3);
    cvt_kernel<<<(HID * HID / 4) / 256, 256>>>(Wo, 4);

    // fused QKV: n spans 3*1024
    gemm_mma_kernel<0><<<dim3(24, 32), 512, G_SMEM>>>(bq, bk, bv, nullptr);

    attn_mma_kernel<<<dim3(S / 128, B * NH), 512, A_SMEM>>>();

    gemm_mma_kernel<1><<<dim3(8, 32), 512, G_SMEM>>>(bo, nullptr, nullptr, out);
}

// round 9
// speedup vs baseline: 1.1534x; 1.1534x over previous
#include <cuda_runtime.h>
#include <cuda_bf16.h>
#include <cstdint>

// Problem constants
constexpr int HID = 1024;
constexpr int NH  = 16;
constexpr int HD  = 64;
constexpr int B   = 2;
constexpr int S   = 2048;
constexpr int M   = B * S;

// ---------------------------------------------------------------------------
// Scratch (__device__ globals; allocation-free rule)
// ---------------------------------------------------------------------------
__device__ __nv_bfloat16 g_xhi[(size_t)M * HID];
__device__ __nv_bfloat16 g_xlo[(size_t)M * HID];
__device__ __nv_bfloat16 g_whi[(size_t)4 * HID * HID];   // [Wq|Wk|Wv|Wo]
__device__ __nv_bfloat16 g_wlo[(size_t)4 * HID * HID];
__device__ __nv_bfloat16 g_qhi[(size_t)M * HID];         // [B,H,S,D], q *0.125
__device__ __nv_bfloat16 g_qlo[(size_t)M * HID];
__device__ __nv_bfloat16 g_khi[(size_t)M * HID];
__device__ __nv_bfloat16 g_klo[(size_t)M * HID];
__device__ __nv_bfloat16 g_vhi[(size_t)M * HID];
__device__ __nv_bfloat16 g_vlo[(size_t)M * HID];
__device__ __nv_bfloat16 g_ahi[(size_t)M * HID];         // attn out [B,S,HID]
__device__ __nv_bfloat16 g_alo[(size_t)M * HID];

// ---------------------------------------------------------------------------
// PTX helpers
// ---------------------------------------------------------------------------
__device__ __forceinline__ uint32_t smem_u32(const void* p) {
    uint32_t a;
    asm("{ .reg .u64 t; cvta.to.shared.u64 t, %1; cvt.u32.u64 %0, t; }"
        : "=r"(a) : "l"(p));
    return a;
}

__device__ __forceinline__ void ldsm_x4(uint32_t (&r)[4], uint32_t addr) {
    asm volatile("ldmatrix.sync.aligned.m8n8.x4.shared.b16 {%0,%1,%2,%3}, [%4];"
                 : "=r"(r[0]), "=r"(r[1]), "=r"(r[2]), "=r"(r[3]) : "r"(addr));
}

__device__ __forceinline__ void ldsm_x4_t(uint32_t (&r)[4], uint32_t addr) {
    asm volatile("ldmatrix.sync.aligned.m8n8.x4.trans.shared.b16 {%0,%1,%2,%3}, [%4];"
                 : "=r"(r[0]), "=r"(r[1]), "=r"(r[2]), "=r"(r[3]) : "r"(addr));
}

__device__ __forceinline__ void mma_bf16(float (&d)[4], const uint32_t (&a)[4],
                                         uint32_t b0, uint32_t b1) {
    asm volatile(
        "mma.sync.aligned.m16n8k16.row.col.f32.bf16.bf16.f32 "
        "{%0,%1,%2,%3}, {%4,%5,%6,%7}, {%8,%9}, {%0,%1,%2,%3};"
        : "+f"(d[0]), "+f"(d[1]), "+f"(d[2]), "+f"(d[3])
        : "r"(a[0]), "r"(a[1]), "r"(a[2]), "r"(a[3]), "r"(b0), "r"(b1));
}

__device__ __forceinline__ void cp16(uint32_t dst, const void* src) {
    asm volatile("cp.async.cg.shared.global [%0], [%1], 16;"
                 :: "r"(dst), "l"(src));
}
#define CP_COMMIT() asm volatile("cp.async.commit_group;")
#define CP_WAIT(n)  asm volatile("cp.async.wait_group %0;" :: "n"(n))

__device__ __forceinline__ uint32_t pack2bf16(float a, float b) {
    __nv_bfloat162 h = __floats2bfloat162_rn(a, b);
    return *reinterpret_cast<uint32_t*>(&h);
}
__device__ __forceinline__ float bf16round(float x) {
    return __bfloat162float(__float2bfloat16(x));
}

// ---------------------------------------------------------------------------
// Pre-pass: split f32 -> bf16 (hi, lo)
// ---------------------------------------------------------------------------
__global__ __launch_bounds__(256)
void cvt_x_kernel(const float* __restrict__ src)
{
    const int i = blockIdx.x * 256 + threadIdx.x;
    float4 v = ((const float4*)src)[i];
    const float hx = bf16round(v.x), hy = bf16round(v.y);
    const float hz = bf16round(v.z), hw = bf16round(v.w);
    ((uint2*)g_xhi)[i] = make_uint2(pack2bf16(v.x, v.y), pack2bf16(v.z, v.w));
    ((uint2*)g_xlo)[i] = make_uint2(pack2bf16(v.x - hx, v.y - hy),
                                    pack2bf16(v.z - hz, v.w - hw));
}

__global__ __launch_bounds__(256)
void cvt_w_kernel(const float* __restrict__ w0, const float* __restrict__ w1,
                  const float* __restrict__ w2, const float* __restrict__ w3)
{
    const int gi  = blockIdx.x * 256 + threadIdx.x;      // 0 .. 4*256K-1
    const int sel = gi >> 18;                            // 256K float4 per W
    const int i   = gi & ((1 << 18) - 1);
    const float* src = (sel == 0) ? w0 : (sel == 1) ? w1 : (sel == 2) ? w2 : w3;
    float4 v = ((const float4*)src)[i];
    const float hx = bf16round(v.x), hy = bf16round(v.y);
    const float hz = bf16round(v.z), hw = bf16round(v.w);
    ((uint2*)g_whi)[gi] = make_uint2(pack2bf16(v.x, v.y), pack2bf16(v.z, v.w));
    ((uint2*)g_wlo)[gi] = make_uint2(pack2bf16(v.x - hx, v.y - hy),
                                     pack2bf16(v.z - hz, v.w - hw));
}

// ---------------------------------------------------------------------------
// GEMM (R6 structure): 256 threads, warp grid 2(M)x4(N), 64x32 warp tiles,
// BK=32, 2-stage cp.async pipeline.
// IS_O=0: fused QKV, n spans 3072 (g_whi rows contiguous across Wq|Wk|Wv);
//         scatter bf16 hi/lo into [B,H,S,D] (q scaled 0.125).
// IS_O=1: O-projection from g_a{hi,lo}; f32 output.
// ---------------------------------------------------------------------------
constexpr int G_TILE  = 128 * 80;      // 10240 B
constexpr int G_STAGE = 4 * G_TILE;    // 40960 B
constexpr int G_SMEM  = 2 * G_STAGE;   // 81920 B

template <int IS_O>
__global__ __launch_bounds__(256, 2)
void gemm_mma_kernel(const float* __restrict__ bq_,
                     const float* __restrict__ bk_,
                     const float* __restrict__ bv_,
                     float* __restrict__ Cout)
{
    extern __shared__ char dynsm[];
    const uint32_t smb = smem_u32(dynsm);

    const __nv_bfloat16* Ahi_g = IS_O ? g_ahi : g_xhi;
    const __nv_bfloat16* Alo_g = IS_O ? g_alo : g_xlo;
    const __nv_bfloat16* Whi_g = g_whi + (IS_O ? (size_t)3 * HID * HID : 0);
    const __nv_bfloat16* Wlo_g = g_wlo + (IS_O ? (size_t)3 * HID * HID : 0);

    const int t      = threadIdx.x;
    const int lane   = t & 31;
    const int wid    = t >> 5;
    const int warp_m = wid >> 2;     // 0..1 -> 64 rows
    const int warp_n = wid & 3;      // 0..3 -> 32 cols
    const int m0 = blockIdx.y * 128;
    const int n0 = blockIdx.x * 128;

    const int a_row = lane & 15;
    const int a_kb  = (lane >> 4) * 16;
    const int b_row = (lane & 7) + ((lane >> 4) << 3);
    const int b_kb  = ((lane >> 3) & 1) * 16;

    const int lr0 = t >> 2;          // 0..63
    const int lj  = t & 3;           // 0..3

    auto load_chunk = [&](int stage, int k0) {
#pragma unroll
        for (int it = 0; it < 2; it++) {
            const int r = lr0 + it * 64;
            const size_t aoff = (size_t)(m0 + r) * HID + k0 + lj * 8;
            const size_t woff = (size_t)(n0 + r) * HID + k0 + lj * 8;
            const uint32_t d = smb + stage * G_STAGE + r * 80 + lj * 16;
            cp16(d,              Ahi_g + aoff);
            cp16(d + G_TILE,     Alo_g + aoff);
            cp16(d + 2 * G_TILE, Whi_g + woff);
            cp16(d + 3 * G_TILE, Wlo_g + woff);
        }
    };

    float acc[4][4][4];
#pragma unroll
    for (int mt = 0; mt < 4; mt++)
#pragma unroll
        for (int nt = 0; nt < 4; nt++)
#pragma unroll
            for (int r = 0; r < 4; r++) acc[mt][nt][r] = 0.f;

    load_chunk(0, 0);
    CP_COMMIT();

    for (int c = 0; c < 32; c++) {
        if (c + 1 < 32) { load_chunk((c + 1) & 1, (c + 1) * 32); CP_COMMIT(); CP_WAIT(1); }
        else            { CP_WAIT(0); }
        __syncthreads();

        const uint32_t sb = smb + (c & 1) * G_STAGE;
#pragma unroll
        for (int ks = 0; ks < 2; ks++) {
            const int ksb = ks * 32;

            uint32_t a_hi[4][4], a_lo[4][4];
#pragma unroll
            for (int mt = 0; mt < 4; mt++) {
                const uint32_t ro =
                    (uint32_t)((warp_m * 64 + mt * 16 + a_row) * 80 + ksb + a_kb);
                ldsm_x4(a_hi[mt], sb + ro);
                ldsm_x4(a_lo[mt], sb + G_TILE + ro);
            }
            uint32_t b_hi[2][4], b_lo[2][4];
#pragma unroll
            for (int bt = 0; bt < 2; bt++) {
                const uint32_t ro =
                    (uint32_t)((warp_n * 32 + bt * 16 + b_row) * 80 + ksb + b_kb);
                ldsm_x4(b_hi[bt], sb + 2 * G_TILE + ro);
                ldsm_x4(b_lo[bt], sb + 3 * G_TILE + ro);
            }

#pragma unroll
            for (int mt = 0; mt < 4; mt++)
#pragma unroll
                for (int nt = 0; nt < 4; nt++) {
                    const int bt = nt >> 1;
                    const int hf = (nt & 1) * 2;
                    mma_bf16(acc[mt][nt], a_hi[mt], b_hi[bt][hf], b_hi[bt][hf + 1]);
                    mma_bf16(acc[mt][nt], a_hi[mt], b_lo[bt][hf], b_lo[bt][hf + 1]);
                    mma_bf16(acc[mt][nt], a_lo[mt], b_hi[bt][hf], b_hi[bt][hf + 1]);
                }
        }
        __syncthreads();
    }

    // ---- epilogue ----
    const int fr = lane >> 2;
    const int fc = (lane & 3) * 2;
#pragma unroll
    for (int mt = 0; mt < 4; mt++)
#pragma unroll
        for (int nt = 0; nt < 4; nt++) {
            const int n_g = n0 + warp_n * 32 + nt * 8 + fc;
            float2 b2;
            float scl = 1.f;
            int w_idx = 0, n_w = n_g;
            if (!IS_O) {
                w_idx = n_g >> 10;
                n_w   = n_g & 1023;
                const float* bias = (w_idx == 0) ? bq_ : (w_idx == 1) ? bk_ : bv_;
                b2 = *(const float2*)&bias[n_w];
                if (w_idx == 0) scl = 0.125f;
            } else {
                b2 = *(const float2*)&bq_[n_g];
            }
#pragma unroll
            for (int p = 0; p < 2; p++) {
                const int m = m0 + warp_m * 64 + mt * 16 + fr + p * 8;
                const float vx = (acc[mt][nt][p * 2 + 0] + b2.x) * scl;
                const float vy = (acc[mt][nt][p * 2 + 1] + b2.y) * scl;
                if (!IS_O) {
                    const int bb = m >> 11;
                    const int ss = m & (S - 1);
                    const int hh = n_w >> 6;
                    const int dd = n_w & 63;
                    const size_t idx =
                        (((size_t)(bb * NH + hh) * S + ss) << 6) + dd;
                    __nv_bfloat16* Chi = (w_idx == 0) ? g_qhi
                                       : (w_idx == 1) ? g_khi : g_vhi;
                    __nv_bfloat16* Clo = (w_idx == 0) ? g_qlo
                                       : (w_idx == 1) ? g_klo : g_vlo;
                    *(uint32_t*)&Chi[idx] = pack2bf16(vx, vy);
                    *(uint32_t*)&Clo[idx] =
                        pack2bf16(vx - bf16round(vx), vy - bf16round(vy));
                } else {
                    float2 v; v.x = vx; v.y = vy;
                    *(float2*)&Cout[(size_t)m * HID + n_g] = v;
                }
            }
        }
}

// ---------------------------------------------------------------------------
// Attention (R6 structure + 2-CTA/SM register cap): 256 threads, 8 warps,
// 128 q rows/CTA, 64-key tiles, 2-stage cp.async pipeline.
// ---------------------------------------------------------------------------
constexpr int KST     = 72;
constexpr int A_TILE  = 64 * KST * 2;     // 9216 B
constexpr int A_STAGE = 4 * A_TILE;       // 36864 B (Khi|Klo|Vhi|Vlo)
constexpr int A_SMEM  = 2 * A_STAGE;      // 73728 B -> 2 CTAs/SM

__global__ __launch_bounds__(256, 2)
void attn_mma_kernel()
{
    extern __shared__ char dynsm[];
    const uint32_t smb = smem_u32(dynsm);

    const int t    = threadIdx.x;
    const int lane = t & 31;
    const int w    = t >> 5;
    const int q0   = (gridDim.x - 1 - blockIdx.x) * 128;  // longest first
    const int bh   = blockIdx.y;
    const int bb   = bh >> 4;
    const int hh   = bh & 15;

    const size_t bh_off = (size_t)bh * S * HD;
    const __nv_bfloat16* Khi_g = g_khi + bh_off;
    const __nv_bfloat16* Klo_g = g_klo + bh_off;
    const __nv_bfloat16* Vhi_g = g_vhi + bh_off;
    const __nv_bfloat16* Vlo_g = g_vlo + bh_off;

    // ---- stage Q via cp.async into stage0, pull fragments to registers ----
    {
#pragma unroll
        for (int it = 0; it < 4; it++) {
            const int i = t + it * 256;      // 0..1023
            const int r = i >> 3;            // 0..127
            const int j = i & 7;
            const size_t off = bh_off + (size_t)(q0 + r) * HD + j * 8;
            const uint32_t d = smb + r * 144 + j * 16;
            cp16(d,             g_qhi + off);
            cp16(d + 128 * 144, g_qlo + off);
        }
        CP_COMMIT();
        CP_WAIT(0);
        __syncthreads();
    }

    const int a_row = lane & 15;
    const int a_kb  = (lane >> 4) * 16;
    uint32_t qhi[4][4], qlo[4][4];
#pragma unroll
    for (int ks = 0; ks < 4; ks++) {
        const uint32_t ro = (uint32_t)((w * 16 + a_row) * 144 + ks * 32 + a_kb);
        ldsm_x4(qhi[ks], smb + ro);
        ldsm_x4(qlo[ks], smb + 128 * 144 + ro);
    }
    __syncthreads();   // all warps done reading Q before stage0 is reused

    const int b_row = (lane & 7) + ((lane >> 4) << 3);
    const int b_kb  = ((lane >> 3) & 1) * 16;

    auto load_tile = [&](int stage, int k0) {
#pragma unroll
        for (int it = 0; it < 2; it++) {
            const int i = t + it * 256;   // 0..511
            const int r = i >> 3;         // 0..63
            const int j = i & 7;
            const size_t off = (size_t)(k0 + r) * HD + j * 8;
            const uint32_t d = smb + stage * A_STAGE + r * 144 + j * 16;
            cp16(d,              Khi_g + off);
            cp16(d + A_TILE,     Klo_g + off);
            cp16(d + 2 * A_TILE, Vhi_g + off);
            cp16(d + 3 * A_TILE, Vlo_g + off);
        }
    };

    float m0 = -1e30f, m1 = -1e30f, l0 = 0.f, l1 = 0.f;
    float oacc[8][4];
#pragma unroll
    for (int nt = 0; nt < 8; nt++)
#pragma unroll
        for (int r = 0; r < 4; r++) oacc[nt][r] = 0.f;

    const int nk = q0 / 64 + 2;
    load_tile(0, 0);
    CP_COMMIT();

    for (int ki = 0; ki < nk; ki++) {
        const int k0 = ki * 64;
        if (ki + 1 < nk) { load_tile((ki + 1) & 1, k0 + 64); CP_COMMIT(); CP_WAIT(1); }
        else             { CP_WAIT(0); }
        __syncthreads();

        const uint32_t sb = smb + (ki & 1) * A_STAGE;

        // ---- S = Q @ K^T (3-term bf16 split) ----
        float sacc[8][4];
#pragma unroll
        for (int nt = 0; nt < 8; nt++)
#pragma unroll
            for (int r = 0; r < 4; r++) sacc[nt][r] = 0.f;

#pragma unroll
        for (int ks = 0; ks < 4; ks++) {
            uint32_t kh[4][4], kl[4][4];
#pragma unroll
            for (int g = 0; g < 4; g++) {
                const uint32_t ro =
                    (uint32_t)((g * 16 + b_row) * 144 + ks * 32 + b_kb);
                ldsm_x4(kh[g], sb + ro);
                ldsm_x4(kl[g], sb + A_TILE + ro);
            }
#pragma unroll
            for (int nt = 0; nt < 8; nt++) {
                const int g  = nt >> 1;
                const int hf = (nt & 1) * 2;
                mma_bf16(sacc[nt], qhi[ks], kh[g][hf], kh[g][hf + 1]);
                mma_bf16(sacc[nt], qhi[ks], kl[g][hf], kl[g][hf + 1]);
                mma_bf16(sacc[nt], qlo[ks], kh[g][hf], kh[g][hf + 1]);
            }
        }

        // ---- causal mask ----
        if (k0 >= q0) {
            const int grow = q0 + w * 16 + (lane >> 2);
#pragma unroll
            for (int nt = 0; nt < 8; nt++) {
                const int gc = k0 + nt * 8 + (lane & 3) * 2;
                if (gc     > grow)     sacc[nt][0] = -1e30f;
                if (gc + 1 > grow)     sacc[nt][1] = -1e30f;
                if (gc     > grow + 8) sacc[nt][2] = -1e30f;
                if (gc + 1 > grow + 8) sacc[nt][3] = -1e30f;
            }
        }

        // ---- online softmax ----
        float mx0 = -1e30f, mx1 = -1e30f;
#pragma unroll
        for (int nt = 0; nt < 8; nt++) {
            mx0 = fmaxf(mx0, fmaxf(sacc[nt][0], sacc[nt][1]));
            mx1 = fmaxf(mx1, fmaxf(sacc[nt][2], sacc[nt][3]));
        }
        mx0 = fmaxf(mx0, __shfl_xor_sync(0xffffffffu, mx0, 1));
        mx0 = fmaxf(mx0, __shfl_xor_sync(0xffffffffu, mx0, 2));
        mx1 = fmaxf(mx1, __shfl_xor_sync(0xffffffffu, mx1, 1));
        mx1 = fmaxf(mx1, __shfl_xor_sync(0xffffffffu, mx1, 2));

        const float mn0 = fmaxf(m0, mx0);
        const float mn1 = fmaxf(m1, mx1);
        float sum0 = 0.f, sum1 = 0.f;
#pragma unroll
        for (int nt = 0; nt < 8; nt++) {
            sacc[nt][0] = __expf(sacc[nt][0] - mn0); sum0 += sacc[nt][0];
            sacc[nt][1] = __expf(sacc[nt][1] - mn0); sum0 += sacc[nt][1];
            sacc[nt][2] = __expf(sacc[nt][2] - mn1); sum1 += sacc[nt][2];
            sacc[nt][3] = __expf(sacc[nt][3] - mn1); sum1 += sacc[nt][3];
        }
        sum0 += __shfl_xor_sync(0xffffffffu, sum0, 1);
        sum0 += __shfl_xor_sync(0xffffffffu, sum0, 2);
        sum1 += __shfl_xor_sync(0xffffffffu, sum1, 1);
        sum1 += __shfl_xor_sync(0xffffffffu, sum1, 2);

        const float sc0 = __expf(m0 - mn0);
        const float sc1 = __expf(m1 - mn1);
        l0 = l0 * sc0 + sum0; m0 = mn0;
        l1 = l1 * sc1 + sum1; m1 = mn1;
#pragma unroll
        for (int nt = 0; nt < 8; nt++) {
            oacc[nt][0] *= sc0; oacc[nt][1] *= sc0;
            oacc[nt][2] *= sc1; oacc[nt][3] *= sc1;
        }

        // ---- O += P @ V ----
#pragma unroll
        for (int ks = 0; ks < 4; ks++) {
            uint32_t ph[4], pl[4];
            {
                const float p00 = sacc[2 * ks][0],     p01 = sacc[2 * ks][1];
                const float p02 = sacc[2 * ks][2],     p03 = sacc[2 * ks][3];
                const float p10 = sacc[2 * ks + 1][0], p11 = sacc[2 * ks + 1][1];
                const float p12 = sacc[2 * ks + 1][2], p13 = sacc[2 * ks + 1][3];
                ph[0] = pack2bf16(p00, p01);
                ph[1] = pack2bf16(p02, p03);
                ph[2] = pack2bf16(p10, p11);
                ph[3] = pack2bf16(p12, p13);
                pl[0] = pack2bf16(p00 - bf16round(p00), p01 - bf16round(p01));
                pl[1] = pack2bf16(p02 - bf16round(p02), p03 - bf16round(p03));
                pl[2] = pack2bf16(p10 - bf16round(p10), p11 - bf16round(p11));
                pl[3] = pack2bf16(p12 - bf16round(p12), p13 - bf16round(p13));
            }
            uint32_t vh[4][4], vl[4][4];
#pragma unroll
            for (int g = 0; g < 4; g++) {
                const uint32_t ro =
                    (uint32_t)((ks * 16 + a_row) * 144 + g * 32 + a_kb);
                ldsm_x4_t(vh[g], sb + 2 * A_TILE + ro);
                ldsm_x4_t(vl[g], sb + 3 * A_TILE + ro);
            }
#pragma unroll
            for (int nt = 0; nt < 8; nt++) {
                const int g  = nt >> 1;
                const int hf = (nt & 1) * 2;
                mma_bf16(oacc[nt], ph, vh[g][hf], vh[g][hf + 1]);
                mma_bf16(oacc[nt], ph, vl[g][hf], vl[g][hf + 1]);
                mma_bf16(oacc[nt], pl, vh[g][hf], vh[g][hf + 1]);
            }
        }
        __syncthreads();
    }

    // ---- finalize + write bf16 hi/lo to g_a{hi,lo} [B,S,HID] ----
    const float il0 = 1.f / l0;
    const float il1 = 1.f / l1;
    const int r0 = q0 + w * 16 + (lane >> 2);
#pragma unroll
    for (int nt = 0; nt < 8; nt++) {
        const int d = nt * 8 + (lane & 3) * 2;
        const float v0x = oacc[nt][0] * il0, v0y = oacc[nt][1] * il0;
        const float v1x = oacc[nt][2] * il1, v1y = oacc[nt][3] * il1;
        const size_t i0 = ((size_t)bb * S + r0) * HID + hh * 64 + d;
        const size_t i1 = ((size_t)bb * S + r0 + 8) * HID + hh * 64 + d;
        *(uint32_t*)&g_ahi[i0] = pack2bf16(v0x, v0y);
        *(uint32_t*)&g_alo[i0] =
            pack2bf16(v0x - bf16round(v0x), v0y - bf16round(v0y));
        *(uint32_t*)&g_ahi[i1] = pack2bf16(v1x, v1y);
        *(uint32_t*)&g_alo[i1] =
            pack2bf16(v1x - bf16round(v1x), v1y - bf16round(v1y));
    }
}

// ---------------------------------------------------------------------------
// Launch
// ---------------------------------------------------------------------------
extern "C" void kernel_launch(void* const* d_in, const int* in_sizes, int n_in,
                              void* d_out, int out_size)
{
    const float* x  = (const float*)d_in[0];
    const float* Wq = (const float*)d_in[1];
    const float* bq = (const float*)d_in[2];
    const float* Wk = (const float*)d_in[3];
    const float* bk = (const float*)d_in[4];
    const float* Wv = (const float*)d_in[5];
    const float* bv = (const float*)d_in[6];
    const float* Wo = (const float*)d_in[7];
    const float* bo = (const float*)d_in[8];
    float* out = (float*)d_out;

    cudaFuncSetAttribute(attn_mma_kernel,
                         cudaFuncAttributeMaxDynamicSharedMemorySize, A_SMEM);
    cudaFuncSetAttribute(gemm_mma_kernel<0>,
                         cudaFuncAttributeMaxDynamicSharedMemorySize, G_SMEM);
    cudaFuncSetAttribute(gemm_mma_kernel<1>,
                         cudaFuncAttributeMaxDynamicSharedMemorySize, G_SMEM);

    cvt_x_kernel<<<(M * HID / 4) / 256, 256>>>(x);
    cvt_w_kernel<<<(4 * HID * HID / 4) / 256, 256>>>(Wq, Wk, Wv, Wo);

    // fused QKV: n spans 3*1024
    gemm_mma_kernel<0><<<dim3(24, 32), 256, G_SMEM>>>(bq, bk, bv, nullptr);

    attn_mma_kernel<<<dim3(S / 128, B * NH), 256, A_SMEM>>>();

    gemm_mma_kernel<1><<<dim3(8, 32), 256, G_SMEM>>>(bo, nullptr, nullptr, out);
}

// round 10
// speedup vs baseline: 1.6240x; 1.4080x over previous
#include <cuda_runtime.h>
#include <cuda_fp16.h>
#include <cstdint>

// Problem constants
constexpr int HID = 1024;
constexpr int NH  = 16;
constexpr int HD  = 64;
constexpr int B   = 2;
constexpr int S   = 2048;
constexpr int M   = B * S;

// ---------------------------------------------------------------------------
// Scratch (__device__ globals; allocation-free rule)
// A-side operands split fp16 hi+lo (exact to ~2^-21); B-side single fp16.
// ---------------------------------------------------------------------------
__device__ __half g_xhi[(size_t)M * HID];
__device__ __half g_xlo[(size_t)M * HID];
__device__ __half g_wh [(size_t)4 * HID * HID];     // [Wq|Wk|Wv|Wo] single
__device__ __half g_qhi[(size_t)M * HID];           // [B,H,S,D], q *0.125
__device__ __half g_qlo[(size_t)M * HID];
__device__ __half g_kh [(size_t)M * HID];           // single
__device__ __half g_vh [(size_t)M * HID];           // single
__device__ __half g_ahi[(size_t)M * HID];           // attn out [B,S,HID]
__device__ __half g_alo[(size_t)M * HID];

// ---------------------------------------------------------------------------
// PTX helpers
// ---------------------------------------------------------------------------
__device__ __forceinline__ uint32_t smem_u32(const void* p) {
    uint32_t a;
    asm("{ .reg .u64 t; cvta.to.shared.u64 t, %1; cvt.u32.u64 %0, t; }"
        : "=r"(a) : "l"(p));
    return a;
}

__device__ __forceinline__ void ldsm_x4(uint32_t (&r)[4], uint32_t addr) {
    asm volatile("ldmatrix.sync.aligned.m8n8.x4.shared.b16 {%0,%1,%2,%3}, [%4];"
                 : "=r"(r[0]), "=r"(r[1]), "=r"(r[2]), "=r"(r[3]) : "r"(addr));
}

__device__ __forceinline__ void ldsm_x4_t(uint32_t (&r)[4], uint32_t addr) {
    asm volatile("ldmatrix.sync.aligned.m8n8.x4.trans.shared.b16 {%0,%1,%2,%3}, [%4];"
                 : "=r"(r[0]), "=r"(r[1]), "=r"(r[2]), "=r"(r[3]) : "r"(addr));
}

__device__ __forceinline__ void mma_f16(float (&d)[4], const uint32_t (&a)[4],
                                        uint32_t b0, uint32_t b1) {
    asm volatile(
        "mma.sync.aligned.m16n8k16.row.col.f32.f16.f16.f32 "
        "{%0,%1,%2,%3}, {%4,%5,%6,%7}, {%8,%9}, {%0,%1,%2,%3};"
        : "+f"(d[0]), "+f"(d[1]), "+f"(d[2]), "+f"(d[3])
        : "r"(a[0]), "r"(a[1]), "r"(a[2]), "r"(a[3]), "r"(b0), "r"(b1));
}

__device__ __forceinline__ void cp16(uint32_t dst, const void* src) {
    asm volatile("cp.async.cg.shared.global [%0], [%1], 16;"
                 :: "r"(dst), "l"(src));
}
#define CP_COMMIT() asm volatile("cp.async.commit_group;")
#define CP_WAIT(n)  asm volatile("cp.async.wait_group %0;" :: "n"(n))

__device__ __forceinline__ uint32_t pack2f16(float a, float b) {
    __half2 h = __floats2half2_rn(a, b);
    return *reinterpret_cast<uint32_t*>(&h);
}
__device__ __forceinline__ float f16round(float x) {
    return __half2float(__float2half_rn(x));
}

// ---------------------------------------------------------------------------
// Pre-pass converts
// ---------------------------------------------------------------------------
__global__ __launch_bounds__(256)
void cvt_x_kernel(const float* __restrict__ src)
{
    const int i = blockIdx.x * 256 + threadIdx.x;
    float4 v = ((const float4*)src)[i];
    const float hx = f16round(v.x), hy = f16round(v.y);
    const float hz = f16round(v.z), hw = f16round(v.w);
    ((uint2*)g_xhi)[i] = make_uint2(pack2f16(v.x, v.y), pack2f16(v.z, v.w));
    ((uint2*)g_xlo)[i] = make_uint2(pack2f16(v.x - hx, v.y - hy),
                                    pack2f16(v.z - hz, v.w - hw));
}

__global__ __launch_bounds__(256)
void cvt_w_kernel(const float* __restrict__ w0, const float* __restrict__ w1,
                  const float* __restrict__ w2, const float* __restrict__ w3)
{
    const int gi  = blockIdx.x * 256 + threadIdx.x;      // float4 index
    const int sel = gi >> 18;                            // 256K float4 per W
    const int i   = gi & ((1 << 18) - 1);
    const float* src = (sel == 0) ? w0 : (sel == 1) ? w1 : (sel == 2) ? w2 : w3;
    float4 v = ((const float4*)src)[i];
    ((uint2*)g_wh)[gi] = make_uint2(pack2f16(v.x, v.y), pack2f16(v.z, v.w));
}

// ---------------------------------------------------------------------------
// GEMM: C = A @ W^T + bias. 256 threads, warp grid 2(M)x4(N), 64x32 warp
// tiles, BK=32, 3-stage cp.async pipeline, ONE __syncthreads per chunk.
// 2 MMAs per k16: a_hi*b + a_lo*b (b = single fp16 weight).
// IS_O=0: fused QKV (n spans 3072) -> q hi/lo (scaled 0.125), k/v single.
// IS_O=1: O-projection from g_a{hi,lo}; f32 output.
// ---------------------------------------------------------------------------
constexpr int G_TILE  = 128 * 80;      // 10240 B per array (128 rows x 80 B)
constexpr int G_STAGE = 3 * G_TILE;    // Ahi | Alo | B  = 30720 B
constexpr int G_SMEM  = 3 * G_STAGE;   // 92160 B -> 2 CTAs/SM

template <int IS_O>
__global__ __launch_bounds__(256, 2)
void gemm_mma_kernel(const float* __restrict__ bq_,
                     const float* __restrict__ bk_,
                     const float* __restrict__ bv_,
                     float* __restrict__ Cout)
{
    extern __shared__ char dynsm[];
    const uint32_t smb = smem_u32(dynsm);

    const __half* Ahi_g = IS_O ? g_ahi : g_xhi;
    const __half* Alo_g = IS_O ? g_alo : g_xlo;
    const __half* W_g   = g_wh + (IS_O ? (size_t)3 * HID * HID : 0);

    const int t      = threadIdx.x;
    const int lane   = t & 31;
    const int wid    = t >> 5;
    const int warp_m = wid >> 2;     // 0..1 -> 64 rows
    const int warp_n = wid & 3;      // 0..3 -> 32 cols
    const int m0 = blockIdx.y * 128;
    const int n0 = blockIdx.x * 128;

    const int a_row = lane & 15;
    const int a_kb  = (lane >> 4) * 16;
    const int b_row = (lane & 7) + ((lane >> 4) << 3);
    const int b_kb  = ((lane >> 3) & 1) * 16;

    const int lr0 = t >> 2;          // 0..63
    const int lj  = t & 3;           // 0..3

    auto load_chunk = [&](int stage, int k0) {
#pragma unroll
        for (int it = 0; it < 2; it++) {
            const int r = lr0 + it * 64;
            const size_t aoff = (size_t)(m0 + r) * HID + k0 + lj * 8;
            const size_t woff = (size_t)(n0 + r) * HID + k0 + lj * 8;
            const uint32_t d = smb + stage * G_STAGE + r * 80 + lj * 16;
            cp16(d,              Ahi_g + aoff);
            cp16(d + G_TILE,     Alo_g + aoff);
            cp16(d + 2 * G_TILE, W_g + woff);
        }
    };

    float acc[4][4][4];
#pragma unroll
    for (int mt = 0; mt < 4; mt++)
#pragma unroll
        for (int nt = 0; nt < 4; nt++)
#pragma unroll
            for (int r = 0; r < 4; r++) acc[mt][nt][r] = 0.f;

    load_chunk(0, 0);  CP_COMMIT();
    load_chunk(1, 32); CP_COMMIT();

    for (int c = 0; c < 32; c++) {
        if (c + 1 < 32) { CP_WAIT(1); } else { CP_WAIT(0); }
        __syncthreads();
        if (c + 2 < 32) { load_chunk((c + 2) % 3, (c + 2) * 32); CP_COMMIT(); }

        const uint32_t sb = smb + (c % 3) * G_STAGE;
#pragma unroll
        for (int ks = 0; ks < 2; ks++) {
            const int ksb = ks * 32;

            uint32_t a_hi[4][4], a_lo[4][4];
#pragma unroll
            for (int mt = 0; mt < 4; mt++) {
                const uint32_t ro =
                    (uint32_t)((warp_m * 64 + mt * 16 + a_row) * 80 + ksb + a_kb);
                ldsm_x4(a_hi[mt], sb + ro);
                ldsm_x4(a_lo[mt], sb + G_TILE + ro);
            }
            uint32_t bw[2][4];
#pragma unroll
            for (int bt = 0; bt < 2; bt++) {
                const uint32_t ro =
                    (uint32_t)((warp_n * 32 + bt * 16 + b_row) * 80 + ksb + b_kb);
                ldsm_x4(bw[bt], sb + 2 * G_TILE + ro);
            }

#pragma unroll
            for (int mt = 0; mt < 4; mt++)
#pragma unroll
                for (int nt = 0; nt < 4; nt++) {
                    const int bt = nt >> 1;
                    const int hf = (nt & 1) * 2;
                    mma_f16(acc[mt][nt], a_hi[mt], bw[bt][hf], bw[bt][hf + 1]);
                    mma_f16(acc[mt][nt], a_lo[mt], bw[bt][hf], bw[bt][hf + 1]);
                }
        }
    }

    // ---- epilogue ----
    const int fr = lane >> 2;
    const int fc = (lane & 3) * 2;
#pragma unroll
    for (int mt = 0; mt < 4; mt++)
#pragma unroll
        for (int nt = 0; nt < 4; nt++) {
            const int n_g = n0 + warp_n * 32 + nt * 8 + fc;
            float2 b2;
            float scl = 1.f;
            int w_idx = 0, n_w = n_g;
            if (!IS_O) {
                w_idx = n_g >> 10;
                n_w   = n_g & 1023;
                const float* bias = (w_idx == 0) ? bq_ : (w_idx == 1) ? bk_ : bv_;
                b2 = *(const float2*)&bias[n_w];
                if (w_idx == 0) scl = 0.125f;
            } else {
                b2 = *(const float2*)&bq_[n_g];
            }
#pragma unroll
            for (int p = 0; p < 2; p++) {
                const int m = m0 + warp_m * 64 + mt * 16 + fr + p * 8;
                const float vx = (acc[mt][nt][p * 2 + 0] + b2.x) * scl;
                const float vy = (acc[mt][nt][p * 2 + 1] + b2.y) * scl;
                if (!IS_O) {
                    const int bb = m >> 11;
                    const int ss = m & (S - 1);
                    const int hh = n_w >> 6;
                    const int dd = n_w & 63;
                    const size_t idx =
                        (((size_t)(bb * NH + hh) * S + ss) << 6) + dd;
                    if (w_idx == 0) {
                        *(uint32_t*)&g_qhi[idx] = pack2f16(vx, vy);
                        *(uint32_t*)&g_qlo[idx] =
                            pack2f16(vx - f16round(vx), vy - f16round(vy));
                    } else if (w_idx == 1) {
                        *(uint32_t*)&g_kh[idx] = pack2f16(vx, vy);
                    } else {
                        *(uint32_t*)&g_vh[idx] = pack2f16(vx, vy);
                    }
                } else {
                    float2 v; v.x = vx; v.y = vy;
                    *(float2*)&Cout[(size_t)m * HID + n_g] = v;
                }
            }
        }
}

// ---------------------------------------------------------------------------
// Attention: 256 threads, 8 warps, 128 q rows/CTA, 64-key tiles, 3-stage
// cp.async pipeline (one sync/tile). Q split fp16 hi/lo (frags in regs);
// K, V single fp16. QK: 2 MMAs/k16; PV: P split hi/lo in regs, 2 MMAs/k16.
// ---------------------------------------------------------------------------
constexpr int A_TILE  = 64 * 144;         // 9216 B (one array)
constexpr int A_STAGE = 2 * A_TILE;       // K | V = 18432 B
constexpr int A_SMEM  = 3 * A_STAGE;      // 55296 B -> 2 CTAs/SM

__global__ __launch_bounds__(256, 2)
void attn_mma_kernel()
{
    extern __shared__ char dynsm[];
    const uint32_t smb = smem_u32(dynsm);

    const int t    = threadIdx.x;
    const int lane = t & 31;
    const int w    = t >> 5;
    const int q0   = (gridDim.x - 1 - blockIdx.x) * 128;  // longest first
    const int bh   = blockIdx.y;
    const int bb   = bh >> 4;
    const int hh   = bh & 15;

    const size_t bh_off = (size_t)bh * S * HD;
    const __half* Kh_g = g_kh + bh_off;
    const __half* Vh_g = g_vh + bh_off;

    // ---- stage Q (hi at smb, lo at smb+A_STAGE region) and pull frags ----
    {
#pragma unroll
        for (int it = 0; it < 4; it++) {
            const int i = t + it * 256;      // 0..1023
            const int r = i >> 3;            // 0..127
            const int j = i & 7;
            const size_t off = bh_off + (size_t)(q0 + r) * HD + j * 8;
            const uint32_t d = smb + r * 144 + j * 16;
            cp16(d,             g_qhi + off);
            cp16(d + 128 * 144, g_qlo + off);
        }
        CP_COMMIT();
        CP_WAIT(0);
        __syncthreads();
    }

    const int a_row = lane & 15;
    const int a_kb  = (lane >> 4) * 16;
    uint32_t qhi[4][4], qlo[4][4];
#pragma unroll
    for (int ks = 0; ks < 4; ks++) {
        const uint32_t ro = (uint32_t)((w * 16 + a_row) * 144 + ks * 32 + a_kb);
        ldsm_x4(qhi[ks], smb + ro);
        ldsm_x4(qlo[ks], smb + 128 * 144 + ro);
    }
    __syncthreads();   // Q fully consumed before tile loads reuse the area

    const int b_row = (lane & 7) + ((lane >> 4) << 3);
    const int b_kb  = ((lane >> 3) & 1) * 16;

    auto load_tile = [&](int stage, int k0) {
#pragma unroll
        for (int it = 0; it < 2; it++) {
            const int i = t + it * 256;   // 0..511
            const int r = i >> 3;         // 0..63
            const int j = i & 7;
            const size_t off = (size_t)(k0 + r) * HD + j * 8;
            const uint32_t d = smb + stage * A_STAGE + r * 144 + j * 16;
            cp16(d,          Kh_g + off);
            cp16(d + A_TILE, Vh_g + off);
        }
    };

    float m0 = -1e30f, m1 = -1e30f, l0 = 0.f, l1 = 0.f;
    float oacc[8][4];
#pragma unroll
    for (int nt = 0; nt < 8; nt++)
#pragma unroll
        for (int r = 0; r < 4; r++) oacc[nt][r] = 0.f;

    const int nk = q0 / 64 + 2;
    load_tile(0, 0);  CP_COMMIT();
    load_tile(1, 64); CP_COMMIT();

    for (int ki = 0; ki < nk; ki++) {
        const int k0 = ki * 64;
        if (ki + 1 < nk) { CP_WAIT(1); } else { CP_WAIT(0); }
        __syncthreads();
        if (ki + 2 < nk) { load_tile((ki + 2) % 3, k0 + 128); CP_COMMIT(); }

        const uint32_t sb = smb + (ki % 3) * A_STAGE;

        // ---- S = Q @ K^T (2-term fp16 split) ----
        float sacc[8][4];
#pragma unroll
        for (int nt = 0; nt < 8; nt++)
#pragma unroll
            for (int r = 0; r < 4; r++) sacc[nt][r] = 0.f;

#pragma unroll
        for (int ks = 0; ks < 4; ks++) {
            uint32_t kh[4][4];
#pragma unroll
            for (int g = 0; g < 4; g++) {
                const uint32_t ro =
                    (uint32_t)((g * 16 + b_row) * 144 + ks * 32 + b_kb);
                ldsm_x4(kh[g], sb + ro);
            }
#pragma unroll
            for (int nt = 0; nt < 8; nt++) {
                const int g  = nt >> 1;
                const int hf = (nt & 1) * 2;
                mma_f16(sacc[nt], qhi[ks], kh[g][hf], kh[g][hf + 1]);
                mma_f16(sacc[nt], qlo[ks], kh[g][hf], kh[g][hf + 1]);
            }
        }

        // ---- causal mask ----
        if (k0 >= q0) {
            const int grow = q0 + w * 16 + (lane >> 2);
#pragma unroll
            for (int nt = 0; nt < 8; nt++) {
                const int gc = k0 + nt * 8 + (lane & 3) * 2;
                if (gc     > grow)     sacc[nt][0] = -1e30f;
                if (gc + 1 > grow)     sacc[nt][1] = -1e30f;
                if (gc     > grow + 8) sacc[nt][2] = -1e30f;
                if (gc + 1 > grow + 8) sacc[nt][3] = -1e30f;
            }
        }

        // ---- online softmax ----
        float mx0 = -1e30f, mx1 = -1e30f;
#pragma unroll
        for (int nt = 0; nt < 8; nt++) {
            mx0 = fmaxf(mx0, fmaxf(sacc[nt][0], sacc[nt][1]));
            mx1 = fmaxf(mx1, fmaxf(sacc[nt][2], sacc[nt][3]));
        }
        mx0 = fmaxf(mx0, __shfl_xor_sync(0xffffffffu, mx0, 1));
        mx0 = fmaxf(mx0, __shfl_xor_sync(0xffffffffu, mx0, 2));
        mx1 = fmaxf(mx1, __shfl_xor_sync(0xffffffffu, mx1, 1));
        mx1 = fmaxf(mx1, __shfl_xor_sync(0xffffffffu, mx1, 2));

        const float mn0 = fmaxf(m0, mx0);
        const float mn1 = fmaxf(m1, mx1);
        float sum0 = 0.f, sum1 = 0.f;
#pragma unroll
        for (int nt = 0; nt < 8; nt++) {
            sacc[nt][0] = __expf(sacc[nt][0] - mn0); sum0 += sacc[nt][0];
            sacc[nt][1] = __expf(sacc[nt][1] - mn0); sum0 += sacc[nt][1];
            sacc[nt][2] = __expf(sacc[nt][2] - mn1); sum1 += sacc[nt][2];
            sacc[nt][3] = __expf(sacc[nt][3] - mn1); sum1 += sacc[nt][3];
        }
        sum0 += __shfl_xor_sync(0xffffffffu, sum0, 1);
        sum0 += __shfl_xor_sync(0xffffffffu, sum0, 2);
        sum1 += __shfl_xor_sync(0xffffffffu, sum1, 1);
        sum1 += __shfl_xor_sync(0xffffffffu, sum1, 2);

        const float sc0 = __expf(m0 - mn0);
        const float sc1 = __expf(m1 - mn1);
        l0 = l0 * sc0 + sum0; m0 = mn0;
        l1 = l1 * sc1 + sum1; m1 = mn1;
#pragma unroll
        for (int nt = 0; nt < 8; nt++) {
            oacc[nt][0] *= sc0; oacc[nt][1] *= sc0;
            oacc[nt][2] *= sc1; oacc[nt][3] *= sc1;
        }

        // ---- O += P @ V  (P split fp16 hi/lo in regs; V single) ----
#pragma unroll
        for (int ks = 0; ks < 4; ks++) {
            uint32_t ph[4], pl[4];
            {
                const float p00 = sacc[2 * ks][0],     p01 = sacc[2 * ks][1];
                const float p02 = sacc[2 * ks][2],     p03 = sacc[2 * ks][3];
                const float p10 = sacc[2 * ks + 1][0], p11 = sacc[2 * ks + 1][1];
                const float p12 = sacc[2 * ks + 1][2], p13 = sacc[2 * ks + 1][3];
                ph[0] = pack2f16(p00, p01);
                ph[1] = pack2f16(p02, p03);
                ph[2] = pack2f16(p10, p11);
                ph[3] = pack2f16(p12, p13);
                pl[0] = pack2f16(p00 - f16round(p00), p01 - f16round(p01));
                pl[1] = pack2f16(p02 - f16round(p02), p03 - f16round(p03));
                pl[2] = pack2f16(p10 - f16round(p10), p11 - f16round(p11));
                pl[3] = pack2f16(p12 - f16round(p12), p13 - f16round(p13));
            }
            uint32_t vh[4][4];
#pragma unroll
            for (int g = 0; g < 4; g++) {
                const uint32_t ro =
                    (uint32_t)((ks * 16 + a_row) * 144 + g * 32 + a_kb);
                ldsm_x4_t(vh[g], sb + A_TILE + ro);
            }
#pragma unroll
            for (int nt = 0; nt < 8; nt++) {
                const int g  = nt >> 1;
                const int hf = (nt & 1) * 2;
                mma_f16(oacc[nt], ph, vh[g][hf], vh[g][hf + 1]);
                mma_f16(oacc[nt], pl, vh[g][hf], vh[g][hf + 1]);
            }
        }
    }

    // ---- finalize + write fp16 hi/lo to g_a{hi,lo} [B,S,HID] ----
    const float il0 = 1.f / l0;
    const float il1 = 1.f / l1;
    const int r0 = q0 + w * 16 + (lane >> 2);
#pragma unroll
    for (int nt = 0; nt < 8; nt++) {
        const int d = nt * 8 + (lane & 3) * 2;
        const float v0x = oacc[nt][0] * il0, v0y = oacc[nt][1] * il0;
        const float v1x = oacc[nt][2] * il1, v1y = oacc[nt][3] * il1;
        const size_t i0 = ((size_t)bb * S + r0) * HID + hh * 64 + d;
        const size_t i1 = ((size_t)bb * S + r0 + 8) * HID + hh * 64 + d;
        *(uint32_t*)&g_ahi[i0] = pack2f16(v0x, v0y);
        *(uint32_t*)&g_alo[i0] =
            pack2f16(v0x - f16round(v0x), v0y - f16round(v0y));
        *(uint32_t*)&g_ahi[i1] = pack2f16(v1x, v1y);
        *(uint32_t*)&g_alo[i1] =
            pack2f16(v1x - f16round(v1x), v1y - f16round(v1y));
    }
}

// ---------------------------------------------------------------------------
// Launch
// ---------------------------------------------------------------------------
extern "C" void kernel_launch(void* const* d_in, const int* in_sizes, int n_in,
                              void* d_out, int out_size)
{
    const float* x  = (const float*)d_in[0];
    const float* Wq = (const float*)d_in[1];
    const float* bq = (const float*)d_in[2];
    const float* Wk = (const float*)d_in[3];
    const float* bk = (const float*)d_in[4];
    const float* Wv = (const float*)d_in[5];
    const float* bv = (const float*)d_in[6];
    const float* Wo = (const float*)d_in[7];
    const float* bo = (const float*)d_in[8];
    float* out = (float*)d_out;

    cudaFuncSetAttribute(attn_mma_kernel,
                         cudaFuncAttributeMaxDynamicSharedMemorySize, A_SMEM);
    cudaFuncSetAttribute(gemm_mma_kernel<0>,
                         cudaFuncAttributeMaxDynamicSharedMemorySize, G_SMEM);
    cudaFuncSetAttribute(gemm_mma_kernel<1>,
                         cudaFuncAttributeMaxDynamicSharedMemorySize, G_SMEM);

    cvt_x_kernel<<<(M * HID / 4) / 256, 256>>>(x);
    cvt_w_kernel<<<(4 * HID * HID / 4) / 256, 256>>>(Wq, Wk, Wv, Wo);

    // fused QKV: n spans 3*1024
    gemm_mma_kernel<0><<<dim3(24, 32), 256, G_SMEM>>>(bq, bk, bv, nullptr);

    attn_mma_kernel<<<dim3(S / 128, B * NH), 256, A_SMEM>>>();

    gemm_mma_kernel<1><<<dim3(8, 32), 256, G_SMEM>>>(bo, nullptr, nullptr, out);
}

// round 11
// speedup vs baseline: 2.7073x; 1.6671x over previous
#include <cuda_runtime.h>
#include <cuda_fp16.h>
#include <cstdint>

// Problem constants
constexpr int HID = 1024;
constexpr int NH  = 16;
constexpr int HD  = 64;
constexpr int B   = 2;
constexpr int S   = 2048;
constexpr int M   = B * S;

// ---------------------------------------------------------------------------
// Scratch (__device__ globals) — all single fp16 now
// ---------------------------------------------------------------------------
__device__ __half g_xh[(size_t)M * HID];
__device__ __half g_wh[(size_t)4 * HID * HID];      // [Wq|Wk|Wv|Wo]
__device__ __half g_q [(size_t)M * HID];            // [B,H,S,D], *0.125
__device__ __half g_k [(size_t)M * HID];
__device__ __half g_v [(size_t)M * HID];
__device__ __half g_a [(size_t)M * HID];            // attn out [B,S,HID]

// ---------------------------------------------------------------------------
// PTX helpers
// ---------------------------------------------------------------------------
__device__ __forceinline__ uint32_t smem_u32(const void* p) {
    uint32_t a;
    asm("{ .reg .u64 t; cvta.to.shared.u64 t, %1; cvt.u32.u64 %0, t; }"
        : "=r"(a) : "l"(p));
    return a;
}

__device__ __forceinline__ void ldsm_x4(uint32_t (&r)[4], uint32_t addr) {
    asm volatile("ldmatrix.sync.aligned.m8n8.x4.shared.b16 {%0,%1,%2,%3}, [%4];"
                 : "=r"(r[0]), "=r"(r[1]), "=r"(r[2]), "=r"(r[3]) : "r"(addr));
}

__device__ __forceinline__ void ldsm_x4_t(uint32_t (&r)[4], uint32_t addr) {
    asm volatile("ldmatrix.sync.aligned.m8n8.x4.trans.shared.b16 {%0,%1,%2,%3}, [%4];"
                 : "=r"(r[0]), "=r"(r[1]), "=r"(r[2]), "=r"(r[3]) : "r"(addr));
}

__device__ __forceinline__ void mma_f16(float (&d)[4], const uint32_t (&a)[4],
                                        uint32_t b0, uint32_t b1) {
    asm volatile(
        "mma.sync.aligned.m16n8k16.row.col.f32.f16.f16.f32 "
        "{%0,%1,%2,%3}, {%4,%5,%6,%7}, {%8,%9}, {%0,%1,%2,%3};"
        : "+f"(d[0]), "+f"(d[1]), "+f"(d[2]), "+f"(d[3])
        : "r"(a[0]), "r"(a[1]), "r"(a[2]), "r"(a[3]), "r"(b0), "r"(b1));
}

__device__ __forceinline__ void cp16(uint32_t dst, const void* src) {
    asm volatile("cp.async.cg.shared.global [%0], [%1], 16;"
                 :: "r"(dst), "l"(src));
}
#define CP_COMMIT() asm volatile("cp.async.commit_group;")
#define CP_WAIT(n)  asm volatile("cp.async.wait_group %0;" :: "n"(n))

__device__ __forceinline__ uint32_t pack2f16(float a, float b) {
    __half2 h = __floats2half2_rn(a, b);
    return *reinterpret_cast<uint32_t*>(&h);
}

// ---------------------------------------------------------------------------
// Pre-pass converts (f32 -> single fp16)
// ---------------------------------------------------------------------------
__global__ __launch_bounds__(256)
void cvt_x_kernel(const float* __restrict__ src)
{
    const int i = blockIdx.x * 256 + threadIdx.x;
    float4 v = ((const float4*)src)[i];
    ((uint2*)g_xh)[i] = make_uint2(pack2f16(v.x, v.y), pack2f16(v.z, v.w));
}

__global__ __launch_bounds__(256)
void cvt_w_kernel(const float* __restrict__ w0, const float* __restrict__ w1,
                  const float* __restrict__ w2, const float* __restrict__ w3)
{
    const int gi  = blockIdx.x * 256 + threadIdx.x;
    const int sel = gi >> 18;                            // 256K float4 per W
    const int i   = gi & ((1 << 18) - 1);
    const float* src = (sel == 0) ? w0 : (sel == 1) ? w1 : (sel == 2) ? w2 : w3;
    float4 v = ((const float4*)src)[i];
    ((uint2*)g_wh)[gi] = make_uint2(pack2f16(v.x, v.y), pack2f16(v.z, v.w));
}

// ---------------------------------------------------------------------------
// GEMM: C = A @ W^T + bias. 256 threads, warp grid 2(M)x4(N), 64x32 warp
// tiles, BK=32, 3-stage cp.async, one __syncthreads per chunk.
// 1 MMA per k16 (single fp16 both sides).
// IS_O=0: fused QKV (n over 3072) -> q (scaled 0.125) / k / v fp16.
// IS_O=1: O-projection from g_a; f32 output.
// ---------------------------------------------------------------------------
constexpr int G_TILE  = 128 * 80;      // 10240 B (128 rows x 80 B)
constexpr int G_STAGE = 2 * G_TILE;    // A | W = 20480 B
constexpr int G_SMEM  = 3 * G_STAGE;   // 61440 B -> 2 CTAs/SM

template <int IS_O>
__global__ __launch_bounds__(256, 2)
void gemm_mma_kernel(const float* __restrict__ bq_,
                     const float* __restrict__ bk_,
                     const float* __restrict__ bv_,
                     float* __restrict__ Cout)
{
    extern __shared__ char dynsm[];
    const uint32_t smb = smem_u32(dynsm);

    const __half* A_g = IS_O ? g_a : g_xh;
    const __half* W_g = g_wh + (IS_O ? (size_t)3 * HID * HID : 0);

    const int t      = threadIdx.x;
    const int lane   = t & 31;
    const int wid    = t >> 5;
    const int warp_m = wid >> 2;     // 0..1 -> 64 rows
    const int warp_n = wid & 3;      // 0..3 -> 32 cols
    const int m0 = blockIdx.y * 128;
    const int n0 = blockIdx.x * 128;

    const int a_row = lane & 15;
    const int a_kb  = (lane >> 4) * 16;
    const int b_row = (lane & 7) + ((lane >> 4) << 3);
    const int b_kb  = ((lane >> 3) & 1) * 16;

    const int lr0 = t >> 2;          // 0..63
    const int lj  = t & 3;           // 0..3

    auto load_chunk = [&](int stage, int k0) {
#pragma unroll
        for (int it = 0; it < 2; it++) {
            const int r = lr0 + it * 64;
            const size_t aoff = (size_t)(m0 + r) * HID + k0 + lj * 8;
            const size_t woff = (size_t)(n0 + r) * HID + k0 + lj * 8;
            const uint32_t d = smb + stage * G_STAGE + r * 80 + lj * 16;
            cp16(d,          A_g + aoff);
            cp16(d + G_TILE, W_g + woff);
        }
    };

    float acc[4][4][4];
#pragma unroll
    for (int mt = 0; mt < 4; mt++)
#pragma unroll
        for (int nt = 0; nt < 4; nt++)
#pragma unroll
            for (int r = 0; r < 4; r++) acc[mt][nt][r] = 0.f;

    load_chunk(0, 0);  CP_COMMIT();
    load_chunk(1, 32); CP_COMMIT();

    for (int c = 0; c < 32; c++) {
        if (c + 1 < 32) { CP_WAIT(1); } else { CP_WAIT(0); }
        __syncthreads();
        if (c + 2 < 32) { load_chunk((c + 2) % 3, (c + 2) * 32); CP_COMMIT(); }

        const uint32_t sb = smb + (c % 3) * G_STAGE;
#pragma unroll
        for (int ks = 0; ks < 2; ks++) {
            const int ksb = ks * 32;

            uint32_t af[4][4];
#pragma unroll
            for (int mt = 0; mt < 4; mt++) {
                const uint32_t ro =
                    (uint32_t)((warp_m * 64 + mt * 16 + a_row) * 80 + ksb + a_kb);
                ldsm_x4(af[mt], sb + ro);
            }
            uint32_t bw[2][4];
#pragma unroll
            for (int bt = 0; bt < 2; bt++) {
                const uint32_t ro =
                    (uint32_t)((warp_n * 32 + bt * 16 + b_row) * 80 + ksb + b_kb);
                ldsm_x4(bw[bt], sb + G_TILE + ro);
            }

#pragma unroll
            for (int mt = 0; mt < 4; mt++)
#pragma unroll
                for (int nt = 0; nt < 4; nt++) {
                    const int bt = nt >> 1;
                    const int hf = (nt & 1) * 2;
                    mma_f16(acc[mt][nt], af[mt], bw[bt][hf], bw[bt][hf + 1]);
                }
        }
    }

    // ---- epilogue ----
    const int fr = lane >> 2;
    const int fc = (lane & 3) * 2;
#pragma unroll
    for (int mt = 0; mt < 4; mt++)
#pragma unroll
        for (int nt = 0; nt < 4; nt++) {
            const int n_g = n0 + warp_n * 32 + nt * 8 + fc;
            float2 b2;
            float scl = 1.f;
            int w_idx = 0, n_w = n_g;
            if (!IS_O) {
                w_idx = n_g >> 10;
                n_w   = n_g & 1023;
                const float* bias = (w_idx == 0) ? bq_ : (w_idx == 1) ? bk_ : bv_;
                b2 = *(const float2*)&bias[n_w];
                if (w_idx == 0) scl = 0.125f;
            } else {
                b2 = *(const float2*)&bq_[n_g];
            }
#pragma unroll
            for (int p = 0; p < 2; p++) {
                const int m = m0 + warp_m * 64 + mt * 16 + fr + p * 8;
                const float vx = (acc[mt][nt][p * 2 + 0] + b2.x) * scl;
                const float vy = (acc[mt][nt][p * 2 + 1] + b2.y) * scl;
                if (!IS_O) {
                    const int bb = m >> 11;
                    const int ss = m & (S - 1);
                    const int hh = n_w >> 6;
                    const int dd = n_w & 63;
                    const size_t idx =
                        (((size_t)(bb * NH + hh) * S + ss) << 6) + dd;
                    __half* C = (w_idx == 0) ? g_q : (w_idx == 1) ? g_k : g_v;
                    *(uint32_t*)&C[idx] = pack2f16(vx, vy);
                } else {
                    float2 v; v.x = vx; v.y = vy;
                    *(float2*)&Cout[(size_t)m * HID + n_g] = v;
                }
            }
        }
}

// ---------------------------------------------------------------------------
// Attention: 256 threads, 8 warps, 128 q rows/CTA, 64-key tiles, 3-stage
// cp.async pipeline. All operands single fp16 -> 1 MMA per k16 step.
// ---------------------------------------------------------------------------
constexpr int A_TILE  = 64 * 144;         // 9216 B
constexpr int A_STAGE = 2 * A_TILE;       // K | V = 18432 B
constexpr int A_SMEM  = 3 * A_STAGE;      // 55296 B -> 2 CTAs/SM

__global__ __launch_bounds__(256, 2)
void attn_mma_kernel()
{
    extern __shared__ char dynsm[];
    const uint32_t smb = smem_u32(dynsm);

    const int t    = threadIdx.x;
    const int lane = t & 31;
    const int w    = t >> 5;
    const int q0   = (gridDim.x - 1 - blockIdx.x) * 128;  // longest first
    const int bh   = blockIdx.y;
    const int bb   = bh >> 4;
    const int hh   = bh & 15;

    const size_t bh_off = (size_t)bh * S * HD;
    const __half* Kh_g = g_k + bh_off;
    const __half* Vh_g = g_v + bh_off;

    // ---- stage Q into stage0 area, pull fragments to registers ----
    {
#pragma unroll
        for (int it = 0; it < 4; it++) {
            const int i = t + it * 256;      // 0..1023 (16B chunks)
            const int r = i >> 3;            // 0..127
            const int j = i & 7;
            const size_t off = bh_off + (size_t)(q0 + r) * HD + j * 8;
            cp16(smb + r * 144 + j * 16, g_q + off);
        }
        CP_COMMIT();
        CP_WAIT(0);
        __syncthreads();
    }

    const int a_row = lane & 15;
    const int a_kb  = (lane >> 4) * 16;
    uint32_t qf[4][4];
#pragma unroll
    for (int ks = 0; ks < 4; ks++) {
        const uint32_t ro = (uint32_t)((w * 16 + a_row) * 144 + ks * 32 + a_kb);
        ldsm_x4(qf[ks], smb + ro);
    }
    __syncthreads();   // Q consumed before tile loads reuse the area

    const int b_row = (lane & 7) + ((lane >> 4) << 3);
    const int b_kb  = ((lane >> 3) & 1) * 16;

    auto load_tile = [&](int stage, int k0) {
#pragma unroll
        for (int it = 0; it < 2; it++) {
            const int i = t + it * 256;   // 0..511
            const int r = i >> 3;         // 0..63
            const int j = i & 7;
            const size_t off = (size_t)(k0 + r) * HD + j * 8;
            const uint32_t d = smb + stage * A_STAGE + r * 144 + j * 16;
            cp16(d,          Kh_g + off);
            cp16(d + A_TILE, Vh_g + off);
        }
    };

    float m0 = -1e30f, m1 = -1e30f, l0 = 0.f, l1 = 0.f;
    float oacc[8][4];
#pragma unroll
    for (int nt = 0; nt < 8; nt++)
#pragma unroll
        for (int r = 0; r < 4; r++) oacc[nt][r] = 0.f;

    const int nk = q0 / 64 + 2;
    load_tile(0, 0);  CP_COMMIT();
    load_tile(1, 64); CP_COMMIT();

    for (int ki = 0; ki < nk; ki++) {
        const int k0 = ki * 64;
        if (ki + 1 < nk) { CP_WAIT(1); } else { CP_WAIT(0); }
        __syncthreads();
        if (ki + 2 < nk) { load_tile((ki + 2) % 3, k0 + 128); CP_COMMIT(); }

        const uint32_t sb = smb + (ki % 3) * A_STAGE;

        // ---- S = Q @ K^T ----
        float sacc[8][4];
#pragma unroll
        for (int nt = 0; nt < 8; nt++)
#pragma unroll
            for (int r = 0; r < 4; r++) sacc[nt][r] = 0.f;

#pragma unroll
        for (int ks = 0; ks < 4; ks++) {
            uint32_t kh[4][4];
#pragma unroll
            for (int g = 0; g < 4; g++) {
                const uint32_t ro =
                    (uint32_t)((g * 16 + b_row) * 144 + ks * 32 + b_kb);
                ldsm_x4(kh[g], sb + ro);
            }
#pragma unroll
            for (int nt = 0; nt < 8; nt++) {
                const int g  = nt >> 1;
                const int hf = (nt & 1) * 2;
                mma_f16(sacc[nt], qf[ks], kh[g][hf], kh[g][hf + 1]);
            }
        }

        // ---- causal mask ----
        if (k0 >= q0) {
            const int grow = q0 + w * 16 + (lane >> 2);
#pragma unroll
            for (int nt = 0; nt < 8; nt++) {
                const int gc = k0 + nt * 8 + (lane & 3) * 2;
                if (gc     > grow)     sacc[nt][0] = -1e30f;
                if (gc + 1 > grow)     sacc[nt][1] = -1e30f;
                if (gc     > grow + 8) sacc[nt][2] = -1e30f;
                if (gc + 1 > grow + 8) sacc[nt][3] = -1e30f;
            }
        }

        // ---- online softmax ----
        float mx0 = -1e30f, mx1 = -1e30f;
#pragma unroll
        for (int nt = 0; nt < 8; nt++) {
            mx0 = fmaxf(mx0, fmaxf(sacc[nt][0], sacc[nt][1]));
            mx1 = fmaxf(mx1, fmaxf(sacc[nt][2], sacc[nt][3]));
        }
        mx0 = fmaxf(mx0, __shfl_xor_sync(0xffffffffu, mx0, 1));
        mx0 = fmaxf(mx0, __shfl_xor_sync(0xffffffffu, mx0, 2));
        mx1 = fmaxf(mx1, __shfl_xor_sync(0xffffffffu, mx1, 1));
        mx1 = fmaxf(mx1, __shfl_xor_sync(0xffffffffu, mx1, 2));

        const float mn0 = fmaxf(m0, mx0);
        const float mn1 = fmaxf(m1, mx1);
        float sum0 = 0.f, sum1 = 0.f;
#pragma unroll
        for (int nt = 0; nt < 8; nt++) {
            sacc[nt][0] = __expf(sacc[nt][0] - mn0); sum0 += sacc[nt][0];
            sacc[nt][1] = __expf(sacc[nt][1] - mn0); sum0 += sacc[nt][1];
            sacc[nt][2] = __expf(sacc[nt][2] - mn1); sum1 += sacc[nt][2];
            sacc[nt][3] = __expf(sacc[nt][3] - mn1); sum1 += sacc[nt][3];
        }
        sum0 += __shfl_xor_sync(0xffffffffu, sum0, 1);
        sum0 += __shfl_xor_sync(0xffffffffu, sum0, 2);
        sum1 += __shfl_xor_sync(0xffffffffu, sum1, 1);
        sum1 += __shfl_xor_sync(0xffffffffu, sum1, 2);

        const float sc0 = __expf(m0 - mn0);
        const float sc1 = __expf(m1 - mn1);
        l0 = l0 * sc0 + sum0; m0 = mn0;
        l1 = l1 * sc1 + sum1; m1 = mn1;
#pragma unroll
        for (int nt = 0; nt < 8; nt++) {
            oacc[nt][0] *= sc0; oacc[nt][1] *= sc0;
            oacc[nt][2] *= sc1; oacc[nt][3] *= sc1;
        }

        // ---- O += P @ V  (P single fp16 in regs; V via ldmatrix.trans) ----
#pragma unroll
        for (int ks = 0; ks < 4; ks++) {
            uint32_t ph[4];
            ph[0] = pack2f16(sacc[2 * ks][0],     sacc[2 * ks][1]);
            ph[1] = pack2f16(sacc[2 * ks][2],     sacc[2 * ks][3]);
            ph[2] = pack2f16(sacc[2 * ks + 1][0], sacc[2 * ks + 1][1]);
            ph[3] = pack2f16(sacc[2 * ks + 1][2], sacc[2 * ks + 1][3]);

            uint32_t vh[4][4];
#pragma unroll
            for (int g = 0; g < 4; g++) {
                const uint32_t ro =
                    (uint32_t)((ks * 16 + a_row) * 144 + g * 32 + a_kb);
                ldsm_x4_t(vh[g], sb + A_TILE + ro);
            }
#pragma unroll
            for (int nt = 0; nt < 8; nt++) {
                const int g  = nt >> 1;
                const int hf = (nt & 1) * 2;
                mma_f16(oacc[nt], ph, vh[g][hf], vh[g][hf + 1]);
            }
        }
    }

    // ---- finalize + write fp16 to g_a [B,S,HID] ----
    const float il0 = 1.f / l0;
    const float il1 = 1.f / l1;
    const int r0 = q0 + w * 16 + (lane >> 2);
#pragma unroll
    for (int nt = 0; nt < 8; nt++) {
        const int d = nt * 8 + (lane & 3) * 2;
        const size_t i0 = ((size_t)bb * S + r0) * HID + hh * 64 + d;
        const size_t i1 = ((size_t)bb * S + r0 + 8) * HID + hh * 64 + d;
        *(uint32_t*)&g_a[i0] = pack2f16(oacc[nt][0] * il0, oacc[nt][1] * il0);
        *(uint32_t*)&g_a[i1] = pack2f16(oacc[nt][2] * il1, oacc[nt][3] * il1);
    }
}

// ---------------------------------------------------------------------------
// Launch
// ---------------------------------------------------------------------------
extern "C" void kernel_launch(void* const* d_in, const int* in_sizes, int n_in,
                              void* d_out, int out_size)
{
    const float* x  = (const float*)d_in[0];
    const float* Wq = (const float*)d_in[1];
    const float* bq = (const float*)d_in[2];
    const float* Wk = (const float*)d_in[3];
    const float* bk = (const float*)d_in[4];
    const float* Wv = (const float*)d_in[5];
    const float* bv = (const float*)d_in[6];
    const float* Wo = (const float*)d_in[7];
    const float* bo = (const float*)d_in[8];
    float* out = (float*)d_out;

    cudaFuncSetAttribute(attn_mma_kernel,
                         cudaFuncAttributeMaxDynamicSharedMemorySize, A_SMEM);
    cudaFuncSetAttribute(gemm_mma_kernel<0>,
                         cudaFuncAttributeMaxDynamicSharedMemorySize, G_SMEM);
    cudaFuncSetAttribute(gemm_mma_kernel<1>,
                         cudaFuncAttributeMaxDynamicSharedMemorySize, G_SMEM);

    cvt_x_kernel<<<(M * HID / 4) / 256, 256>>>(x);
    cvt_w_kernel<<<(4 * HID * HID / 4) / 256, 256>>>(Wq, Wk, Wv, Wo);

    // fused QKV: n spans 3*1024
    gemm_mma_kernel<0><<<dim3(24, 32), 256, G_SMEM>>>(bq, bk, bv, nullptr);

    attn_mma_kernel<<<dim3(S / 128, B * NH), 256, A_SMEM>>>();

    gemm_mma_kernel<1><<<dim3(8, 32), 256, G_SMEM>>>(bo, nullptr, nullptr, out);
}

// round 12
// speedup vs baseline: 2.9657x; 1.0954x over previous
#include <cuda_runtime.h>
#include <cuda_fp16.h>
#include <cstdint>

// Problem constants
constexpr int HID = 1024;
constexpr int NH  = 16;
constexpr int HD  = 64;
constexpr int B   = 2;
constexpr int S   = 2048;
constexpr int M   = B * S;

// ---------------------------------------------------------------------------
// Scratch (__device__ globals) — single fp16
// ---------------------------------------------------------------------------
__device__ __half g_xh[(size_t)M * HID];
__device__ __half g_wh[(size_t)4 * HID * HID];      // [Wq|Wk|Wv|Wo]
__device__ __half g_q [(size_t)M * HID];            // [B,H,S,D], *0.125*log2e
__device__ __half g_k [(size_t)M * HID];
__device__ __half g_v [(size_t)M * HID];
__device__ __half g_a [(size_t)M * HID];            // attn out [B,S,HID]

// ---------------------------------------------------------------------------
// PTX helpers
// ---------------------------------------------------------------------------
__device__ __forceinline__ uint32_t smem_u32(const void* p) {
    uint32_t a;
    asm("{ .reg .u64 t; cvta.to.shared.u64 t, %1; cvt.u32.u64 %0, t; }"
        : "=r"(a) : "l"(p));
    return a;
}

__device__ __forceinline__ void ldsm_x4(uint32_t (&r)[4], uint32_t addr) {
    asm volatile("ldmatrix.sync.aligned.m8n8.x4.shared.b16 {%0,%1,%2,%3}, [%4];"
                 : "=r"(r[0]), "=r"(r[1]), "=r"(r[2]), "=r"(r[3]) : "r"(addr));
}

__device__ __forceinline__ void ldsm_x4_t(uint32_t (&r)[4], uint32_t addr) {
    asm volatile("ldmatrix.sync.aligned.m8n8.x4.trans.shared.b16 {%0,%1,%2,%3}, [%4];"
                 : "=r"(r[0]), "=r"(r[1]), "=r"(r[2]), "=r"(r[3]) : "r"(addr));
}

__device__ __forceinline__ void mma_f16(float (&d)[4], const uint32_t (&a)[4],
                                        uint32_t b0, uint32_t b1) {
    asm volatile(
        "mma.sync.aligned.m16n8k16.row.col.f32.f16.f16.f32 "
        "{%0,%1,%2,%3}, {%4,%5,%6,%7}, {%8,%9}, {%0,%1,%2,%3};"
        : "+f"(d[0]), "+f"(d[1]), "+f"(d[2]), "+f"(d[3])
        : "r"(a[0]), "r"(a[1]), "r"(a[2]), "r"(a[3]), "r"(b0), "r"(b1));
}

__device__ __forceinline__ void cp16(uint32_t dst, const void* src) {
    asm volatile("cp.async.cg.shared.global [%0], [%1], 16;"
                 :: "r"(dst), "l"(src));
}
#define CP_COMMIT() asm volatile("cp.async.commit_group;")
#define CP_WAIT(n)  asm volatile("cp.async.wait_group %0;" :: "n"(n))

__device__ __forceinline__ uint32_t pack2f16(float a, float b) {
    __half2 h = __floats2half2_rn(a, b);
    return *reinterpret_cast<uint32_t*>(&h);
}

// ---------------------------------------------------------------------------
// Pre-pass: one launch converts x AND all four W matrices to fp16.
// ---------------------------------------------------------------------------
constexpr int X_F4 = M * HID / 4;            // 1M float4
constexpr int W_F4 = HID * HID / 4;          // 256K float4 per W

__global__ __launch_bounds__(256)
void cvt_kernel(const float* __restrict__ x,
                const float* __restrict__ w0, const float* __restrict__ w1,
                const float* __restrict__ w2, const float* __restrict__ w3)
{
    const int gi = blockIdx.x * 256 + threadIdx.x;
    if (gi < X_F4) {
        float4 v = ((const float4*)x)[gi];
        ((uint2*)g_xh)[gi] = make_uint2(pack2f16(v.x, v.y), pack2f16(v.z, v.w));
    } else {
        const int wi  = gi - X_F4;
        const int sel = wi >> 18;
        const int i   = wi & ((1 << 18) - 1);
        const float* src = (sel == 0) ? w0 : (sel == 1) ? w1
                         : (sel == 2) ? w2 : w3;
        float4 v = ((const float4*)src)[i];
        ((uint2*)g_wh)[wi] = make_uint2(pack2f16(v.x, v.y), pack2f16(v.z, v.w));
    }
}

// ---------------------------------------------------------------------------
// GEMM: C = A @ W^T + bias. 256 threads, warp grid 2(M)x4(N), 64x32 warp
// tiles, BK=64, 3-stage cp.async, ONE __syncthreads per 64-k chunk (16 total).
// IS_O=0: fused QKV (n over 3072) -> q (scaled 0.125*log2e) / k / v fp16.
// IS_O=1: O-projection from g_a; f32 output.
// ---------------------------------------------------------------------------
constexpr int G_TILE  = 128 * 144;     // 18432 B (128 rows x 144 B: 64+8 pad)
constexpr int G_STAGE = 2 * G_TILE;    // A | W = 36864 B
constexpr int G_SMEM  = 3 * G_STAGE;   // 110592 B -> 2 CTAs/SM

constexpr float QSCALE = 0.125f * 1.44269504088896f;   // 1/sqrt(64) * log2(e)

template <int IS_O>
__global__ __launch_bounds__(256, 2)
void gemm_mma_kernel(const float* __restrict__ bq_,
                     const float* __restrict__ bk_,
                     const float* __restrict__ bv_,
                     float* __restrict__ Cout)
{
    extern __shared__ char dynsm[];
    const uint32_t smb = smem_u32(dynsm);

    const __half* A_g = IS_O ? g_a : g_xh;
    const __half* W_g = g_wh + (IS_O ? (size_t)3 * HID * HID : 0);

    const int t      = threadIdx.x;
    const int lane   = t & 31;
    const int wid    = t >> 5;
    const int warp_m = wid >> 2;     // 0..1 -> 64 rows
    const int warp_n = wid & 3;      // 0..3 -> 32 cols
    const int m0 = blockIdx.y * 128;
    const int n0 = blockIdx.x * 128;

    const int a_row = lane & 15;
    const int a_kb  = (lane >> 4) * 16;
    const int b_row = (lane & 7) + ((lane >> 4) << 3);
    const int b_kb  = ((lane >> 3) & 1) * 16;

    // loader: 1024 16B-chunks per array per 64-k chunk; 4 per thread
    const int lr = t >> 3;           // base row 0..31 (advance by 32)
    const int lj = t & 7;            // 16B chunk 0..7 within 128B row

    auto load_chunk = [&](int stage, int k0) {
#pragma unroll
        for (int it = 0; it < 4; it++) {
            const int r = lr + it * 32;
            const size_t aoff = (size_t)(m0 + r) * HID + k0 + lj * 8;
            const size_t woff = (size_t)(n0 + r) * HID + k0 + lj * 8;
            const uint32_t d = smb + stage * G_STAGE + r * 144 + lj * 16;
            cp16(d,          A_g + aoff);
            cp16(d + G_TILE, W_g + woff);
        }
    };

    float acc[4][4][4];
#pragma unroll
    for (int mt = 0; mt < 4; mt++)
#pragma unroll
        for (int nt = 0; nt < 4; nt++)
#pragma unroll
            for (int r = 0; r < 4; r++) acc[mt][nt][r] = 0.f;

    load_chunk(0, 0);   CP_COMMIT();
    load_chunk(1, 64);  CP_COMMIT();

    for (int c = 0; c < 16; c++) {
        if (c + 1 < 16) { CP_WAIT(1); } else { CP_WAIT(0); }
        __syncthreads();
        if (c + 2 < 16) { load_chunk((c + 2) % 3, (c + 2) * 64); CP_COMMIT(); }

        const uint32_t sb = smb + (c % 3) * G_STAGE;
#pragma unroll
        for (int ks = 0; ks < 4; ks++) {
            const int ksb = ks * 32;

            uint32_t af[4][4];
#pragma unroll
            for (int mt = 0; mt < 4; mt++) {
                const uint32_t ro =
                    (uint32_t)((warp_m * 64 + mt * 16 + a_row) * 144 + ksb + a_kb);
                ldsm_x4(af[mt], sb + ro);
            }
            uint32_t bw[2][4];
#pragma unroll
            for (int bt = 0; bt < 2; bt++) {
                const uint32_t ro =
                    (uint32_t)((warp_n * 32 + bt * 16 + b_row) * 144 + ksb + b_kb);
                ldsm_x4(bw[bt], sb + G_TILE + ro);
            }

#pragma unroll
            for (int mt = 0; mt < 4; mt++)
#pragma unroll
                for (int nt = 0; nt < 4; nt++) {
                    const int bt = nt >> 1;
                    const int hf = (nt & 1) * 2;
                    mma_f16(acc[mt][nt], af[mt], bw[bt][hf], bw[bt][hf + 1]);
                }
        }
    }

    // ---- epilogue ----
    const int fr = lane >> 2;
    const int fc = (lane & 3) * 2;
#pragma unroll
    for (int mt = 0; mt < 4; mt++)
#pragma unroll
        for (int nt = 0; nt < 4; nt++) {
            const int n_g = n0 + warp_n * 32 + nt * 8 + fc;
            float2 b2;
            float scl = 1.f;
            int w_idx = 0, n_w = n_g;
            if (!IS_O) {
                w_idx = n_g >> 10;
                n_w   = n_g & 1023;
                const float* bias = (w_idx == 0) ? bq_ : (w_idx == 1) ? bk_ : bv_;
                b2 = *(const float2*)&bias[n_w];
                if (w_idx == 0) scl = QSCALE;
            } else {
                b2 = *(const float2*)&bq_[n_g];
            }
#pragma unroll
            for (int p = 0; p < 2; p++) {
                const int m = m0 + warp_m * 64 + mt * 16 + fr + p * 8;
                const float vx = (acc[mt][nt][p * 2 + 0] + b2.x) * scl;
                const float vy = (acc[mt][nt][p * 2 + 1] + b2.y) * scl;
                if (!IS_O) {
                    const int bb = m >> 11;
                    const int ss = m & (S - 1);
                    const int hh = n_w >> 6;
                    const int dd = n_w & 63;
                    const size_t idx =
                        (((size_t)(bb * NH + hh) * S + ss) << 6) + dd;
                    __half* C = (w_idx == 0) ? g_q : (w_idx == 1) ? g_k : g_v;
                    *(uint32_t*)&C[idx] = pack2f16(vx, vy);
                } else {
                    float2 v; v.x = vx; v.y = vy;
                    *(float2*)&Cout[(size_t)m * HID + n_g] = v;
                }
            }
        }
}

// ---------------------------------------------------------------------------
// Attention: 256 threads, 8 warps, 128 q rows/CTA, 64-key tiles, 3-stage
// cp.async pipeline. Single fp16 operands; softmax in log2 domain
// (q pre-scaled by 0.125*log2e, exp2f instead of expf).
// ---------------------------------------------------------------------------
constexpr int A_TILE  = 64 * 144;         // 9216 B
constexpr int A_STAGE = 2 * A_TILE;       // K | V = 18432 B
constexpr int A_SMEM  = 3 * A_STAGE;      // 55296 B -> 2 CTAs/SM

__global__ __launch_bounds__(256, 2)
void attn_mma_kernel()
{
    extern __shared__ char dynsm[];
    const uint32_t smb = smem_u32(dynsm);

    const int t    = threadIdx.x;
    const int lane = t & 31;
    const int w    = t >> 5;
    const int q0   = (gridDim.x - 1 - blockIdx.x) * 128;  // longest first
    const int bh   = blockIdx.y;
    const int bb   = bh >> 4;
    const int hh   = bh & 15;

    const size_t bh_off = (size_t)bh * S * HD;
    const __half* Kh_g = g_k + bh_off;
    const __half* Vh_g = g_v + bh_off;

    // ---- stage Q into stage0 area, pull fragments to registers ----
    {
#pragma unroll
        for (int it = 0; it < 4; it++) {
            const int i = t + it * 256;      // 0..1023 (16B chunks)
            const int r = i >> 3;            // 0..127
            const int j = i & 7;
            const size_t off = bh_off + (size_t)(q0 + r) * HD + j * 8;
            cp16(smb + r * 144 + j * 16, g_q + off);
        }
        CP_COMMIT();
        CP_WAIT(0);
        __syncthreads();
    }

    const int a_row = lane & 15;
    const int a_kb  = (lane >> 4) * 16;
    uint32_t qf[4][4];
#pragma unroll
    for (int ks = 0; ks < 4; ks++) {
        const uint32_t ro = (uint32_t)((w * 16 + a_row) * 144 + ks * 32 + a_kb);
        ldsm_x4(qf[ks], smb + ro);
    }
    __syncthreads();   // Q consumed before tile loads reuse the area

    const int b_row = (lane & 7) + ((lane >> 4) << 3);
    const int b_kb  = ((lane >> 3) & 1) * 16;

    auto load_tile = [&](int stage, int k0) {
#pragma unroll
        for (int it = 0; it < 2; it++) {
            const int i = t + it * 256;   // 0..511
            const int r = i >> 3;         // 0..63
            const int j = i & 7;
            const size_t off = (size_t)(k0 + r) * HD + j * 8;
            const uint32_t d = smb + stage * A_STAGE + r * 144 + j * 16;
            cp16(d,          Kh_g + off);
            cp16(d + A_TILE, Vh_g + off);
        }
    };

    float m0 = -1e30f, m1 = -1e30f, l0 = 0.f, l1 = 0.f;
    float oacc[8][4];
#pragma unroll
    for (int nt = 0; nt < 8; nt++)
#pragma unroll
        for (int r = 0; r < 4; r++) oacc[nt][r] = 0.f;

    const int nk = q0 / 64 + 2;
    load_tile(0, 0);  CP_COMMIT();
    load_tile(1, 64); CP_COMMIT();

    for (int ki = 0; ki < nk; ki++) {
        const int k0 = ki * 64;
        if (ki + 1 < nk) { CP_WAIT(1); } else { CP_WAIT(0); }
        __syncthreads();
        if (ki + 2 < nk) { load_tile((ki + 2) % 3, k0 + 128); CP_COMMIT(); }

        const uint32_t sb = smb + (ki % 3) * A_STAGE;

        // ---- S = Q @ K^T (log2-domain scores) ----
        float sacc[8][4];
#pragma unroll
        for (int nt = 0; nt < 8; nt++)
#pragma unroll
            for (int r = 0; r < 4; r++) sacc[nt][r] = 0.f;

#pragma unroll
        for (int ks = 0; ks < 4; ks++) {
            uint32_t kh[4][4];
#pragma unroll
            for (int g = 0; g < 4; g++) {
                const uint32_t ro =
                    (uint32_t)((g * 16 + b_row) * 144 + ks * 32 + b_kb);
                ldsm_x4(kh[g], sb + ro);
            }
#pragma unroll
            for (int nt = 0; nt < 8; nt++) {
                const int g  = nt >> 1;
                const int hf = (nt & 1) * 2;
                mma_f16(sacc[nt], qf[ks], kh[g][hf], kh[g][hf + 1]);
            }
        }

        // ---- causal mask ----
        if (k0 >= q0) {
            const int grow = q0 + w * 16 + (lane >> 2);
#pragma unroll
            for (int nt = 0; nt < 8; nt++) {
                const int gc = k0 + nt * 8 + (lane & 3) * 2;
                if (gc     > grow)     sacc[nt][0] = -1e30f;
                if (gc + 1 > grow)     sacc[nt][1] = -1e30f;
                if (gc     > grow + 8) sacc[nt][2] = -1e30f;
                if (gc + 1 > grow + 8) sacc[nt][3] = -1e30f;
            }
        }

        // ---- online softmax (base-2) ----
        float mx0 = -1e30f, mx1 = -1e30f;
#pragma unroll
        for (int nt = 0; nt < 8; nt++) {
            mx0 = fmaxf(mx0, fmaxf(sacc[nt][0], sacc[nt][1]));
            mx1 = fmaxf(mx1, fmaxf(sacc[nt][2], sacc[nt][3]));
        }
        mx0 = fmaxf(mx0, __shfl_xor_sync(0xffffffffu, mx0, 1));
        mx0 = fmaxf(mx0, __shfl_xor_sync(0xffffffffu, mx0, 2));
        mx1 = fmaxf(mx1, __shfl_xor_sync(0xffffffffu, mx1, 1));
        mx1 = fmaxf(mx1, __shfl_xor_sync(0xffffffffu, mx1, 2));

        const float mn0 = fmaxf(m0, mx0);
        const float mn1 = fmaxf(m1, mx1);
        float sum0 = 0.f, sum1 = 0.f;
#pragma unroll
        for (int nt = 0; nt < 8; nt++) {
            sacc[nt][0] = exp2f(sacc[nt][0] - mn0); sum0 += sacc[nt][0];
            sacc[nt][1] = exp2f(sacc[nt][1] - mn0); sum0 += sacc[nt][1];
            sacc[nt][2] = exp2f(sacc[nt][2] - mn1); sum1 += sacc[nt][2];
            sacc[nt][3] = exp2f(sacc[nt][3] - mn1); sum1 += sacc[nt][3];
        }
        sum0 += __shfl_xor_sync(0xffffffffu, sum0, 1);
        sum0 += __shfl_xor_sync(0xffffffffu, sum0, 2);
        sum1 += __shfl_xor_sync(0xffffffffu, sum1, 1);
        sum1 += __shfl_xor_sync(0xffffffffu, sum1, 2);

        const float sc0 = exp2f(m0 - mn0);
        const float sc1 = exp2f(m1 - mn1);
        l0 = l0 * sc0 + sum0; m0 = mn0;
        l1 = l1 * sc1 + sum1; m1 = mn1;
#pragma unroll
        for (int nt = 0; nt < 8; nt++) {
            oacc[nt][0] *= sc0; oacc[nt][1] *= sc0;
            oacc[nt][2] *= sc1; oacc[nt][3] *= sc1;
        }

        // ---- O += P @ V ----
#pragma unroll
        for (int ks = 0; ks < 4; ks++) {
            uint32_t ph[4];
            ph[0] = pack2f16(sacc[2 * ks][0],     sacc[2 * ks][1]);
            ph[1] = pack2f16(sacc[2 * ks][2],     sacc[2 * ks][3]);
            ph[2] = pack2f16(sacc[2 * ks + 1][0], sacc[2 * ks + 1][1]);
            ph[3] = pack2f16(sacc[2 * ks + 1][2], sacc[2 * ks + 1][3]);

            uint32_t vh[4][4];
#pragma unroll
            for (int g = 0; g < 4; g++) {
                const uint32_t ro =
                    (uint32_t)((ks * 16 + a_row) * 144 + g * 32 + a_kb);
                ldsm_x4_t(vh[g], sb + A_TILE + ro);
            }
#pragma unroll
            for (int nt = 0; nt < 8; nt++) {
                const int g  = nt >> 1;
                const int hf = (nt & 1) * 2;
                mma_f16(oacc[nt], ph, vh[g][hf], vh[g][hf + 1]);
            }
        }
    }

    // ---- finalize + write fp16 to g_a [B,S,HID] ----
    const float il0 = 1.f / l0;
    const float il1 = 1.f / l1;
    const int r0 = q0 + w * 16 + (lane >> 2);
#pragma unroll
    for (int nt = 0; nt < 8; nt++) {
        const int d = nt * 8 + (lane & 3) * 2;
        const size_t i0 = ((size_t)bb * S + r0) * HID + hh * 64 + d;
        const size_t i1 = ((size_t)bb * S + r0 + 8) * HID + hh * 64 + d;
        *(uint32_t*)&g_a[i0] = pack2f16(oacc[nt][0] * il0, oacc[nt][1] * il0);
        *(uint32_t*)&g_a[i1] = pack2f16(oacc[nt][2] * il1, oacc[nt][3] * il1);
    }
}

// ---------------------------------------------------------------------------
// Launch
// ---------------------------------------------------------------------------
extern "C" void kernel_launch(void* const* d_in, const int* in_sizes, int n_in,
                              void* d_out, int out_size)
{
    const float* x  = (const float*)d_in[0];
    const float* Wq = (const float*)d_in[1];
    const float* bq = (const float*)d_in[2];
    const float* Wk = (const float*)d_in[3];
    const float* bk = (const float*)d_in[4];
    const float* Wv = (const float*)d_in[5];
    const float* bv = (const float*)d_in[6];
    const float* Wo = (const float*)d_in[7];
    const float* bo = (const float*)d_in[8];
    float* out = (float*)d_out;

    cudaFuncSetAttribute(attn_mma_kernel,
                         cudaFuncAttributeMaxDynamicSharedMemorySize, A_SMEM);
    cudaFuncSetAttribute(gemm_mma_kernel<0>,
                         cudaFuncAttributeMaxDynamicSharedMemorySize, G_SMEM);
    cudaFuncSetAttribute(gemm_mma_kernel<1>,
                         cudaFuncAttributeMaxDynamicSharedMemorySize, G_SMEM);

    cvt_kernel<<<(X_F4 + 4 * W_F4) / 256, 256>>>(x, Wq, Wk, Wv, Wo);

    // fused QKV: n spans 3*1024
    gemm_mma_kernel<0><<<dim3(24, 32), 256, G_SMEM>>>(bq, bk, bv, nullptr);

    attn_mma_kernel<<<dim3(S / 128, B * NH), 256, A_SMEM>>>();

    gemm_mma_kernel<1><<<dim3(8, 32), 256, G_SMEM>>>(bo, nullptr, nullptr, out);
}

// round 13
// speedup vs baseline: 3.0294x; 1.0215x over previous
#include <cuda_runtime.h>
#include <cuda_fp16.h>
#include <cstdint>

// Problem constants
constexpr int HID = 1024;
constexpr int NH  = 16;
constexpr int HD  = 64;
constexpr int B   = 2;
constexpr int S   = 2048;
constexpr int M   = B * S;

// ---------------------------------------------------------------------------
// Scratch (__device__ globals) — single fp16
// ---------------------------------------------------------------------------
__device__ __half g_xh[(size_t)M * HID];
__device__ __half g_wh[(size_t)4 * HID * HID];      // [Wq|Wk|Wv|Wo]
__device__ __half g_q [(size_t)M * HID];            // [B,H,S,D], *0.125*log2e
__device__ __half g_k [(size_t)M * HID];
__device__ __half g_v [(size_t)M * HID];
__device__ __half g_a [(size_t)M * HID];            // attn out [B,S,HID]

// ---------------------------------------------------------------------------
// PTX helpers
// ---------------------------------------------------------------------------
__device__ __forceinline__ uint32_t smem_u32(const void* p) {
    uint32_t a;
    asm("{ .reg .u64 t; cvta.to.shared.u64 t, %1; cvt.u32.u64 %0, t; }"
        : "=r"(a) : "l"(p));
    return a;
}

__device__ __forceinline__ void ldsm_x4(uint32_t (&r)[4], uint32_t addr) {
    asm volatile("ldmatrix.sync.aligned.m8n8.x4.shared.b16 {%0,%1,%2,%3}, [%4];"
                 : "=r"(r[0]), "=r"(r[1]), "=r"(r[2]), "=r"(r[3]) : "r"(addr));
}

__device__ __forceinline__ void ldsm_x4_t(uint32_t (&r)[4], uint32_t addr) {
    asm volatile("ldmatrix.sync.aligned.m8n8.x4.trans.shared.b16 {%0,%1,%2,%3}, [%4];"
                 : "=r"(r[0]), "=r"(r[1]), "=r"(r[2]), "=r"(r[3]) : "r"(addr));
}

__device__ __forceinline__ void ldsm_x2_t(uint32_t (&r)[2], uint32_t addr) {
    asm volatile("ldmatrix.sync.aligned.m8n8.x2.trans.shared.b16 {%0,%1}, [%2];"
                 : "=r"(r[0]), "=r"(r[1]) : "r"(addr));
}

__device__ __forceinline__ void mma_f16(float (&d)[4], const uint32_t (&a)[4],
                                        uint32_t b0, uint32_t b1) {
    asm volatile(
        "mma.sync.aligned.m16n8k16.row.col.f32.f16.f16.f32 "
        "{%0,%1,%2,%3}, {%4,%5,%6,%7}, {%8,%9}, {%0,%1,%2,%3};"
        : "+f"(d[0]), "+f"(d[1]), "+f"(d[2]), "+f"(d[3])
        : "r"(a[0]), "r"(a[1]), "r"(a[2]), "r"(a[3]), "r"(b0), "r"(b1));
}

__device__ __forceinline__ void cp16(uint32_t dst, const void* src) {
    asm volatile("cp.async.cg.shared.global [%0], [%1], 16;"
                 :: "r"(dst), "l"(src));
}
#define CP_COMMIT() asm volatile("cp.async.commit_group;")
#define CP_WAIT(n)  asm volatile("cp.async.wait_group %0;" :: "n"(n))

__device__ __forceinline__ uint32_t pack2f16(float a, float b) {
    __half2 h = __floats2half2_rn(a, b);
    return *reinterpret_cast<uint32_t*>(&h);
}

__device__ __forceinline__ uint32_t ex2_f16x2(uint32_t x) {
    uint32_t r;
    asm("ex2.approx.f16x2 %0, %1;" : "=r"(r) : "r"(x));
    return r;
}

// ---------------------------------------------------------------------------
// Pre-pass: one launch converts x AND all four W matrices to fp16.
// ---------------------------------------------------------------------------
constexpr int X_F4 = M * HID / 4;            // 1M float4
constexpr int W_F4 = HID * HID / 4;          // 256K float4 per W

__global__ __launch_bounds__(256)
void cvt_kernel(const float* __restrict__ x,
                const float* __restrict__ w0, const float* __restrict__ w1,
                const float* __restrict__ w2, const float* __restrict__ w3)
{
    const int gi = blockIdx.x * 256 + threadIdx.x;
    if (gi < X_F4) {
        float4 v = ((const float4*)x)[gi];
        ((uint2*)g_xh)[gi] = make_uint2(pack2f16(v.x, v.y), pack2f16(v.z, v.w));
    } else {
        const int wi  = gi - X_F4;
        const int sel = wi >> 18;
        const int i   = wi & ((1 << 18) - 1);
        const float* src = (sel == 0) ? w0 : (sel == 1) ? w1
                         : (sel == 2) ? w2 : w3;
        float4 v = ((const float4*)src)[i];
        ((uint2*)g_wh)[wi] = make_uint2(pack2f16(v.x, v.y), pack2f16(v.z, v.w));
    }
}

// ---------------------------------------------------------------------------
// GEMM (unchanged from R11): BK=64, 3-stage cp.async, 16 syncs total.
// ---------------------------------------------------------------------------
constexpr int G_TILE  = 128 * 144;     // 18432 B
constexpr int G_STAGE = 2 * G_TILE;    // 36864 B
constexpr int G_SMEM  = 3 * G_STAGE;   // 110592 B -> 2 CTAs/SM

constexpr float QSCALE = 0.125f * 1.44269504088896f;   // 1/sqrt(64) * log2(e)

template <int IS_O>
__global__ __launch_bounds__(256, 2)
void gemm_mma_kernel(const float* __restrict__ bq_,
                     const float* __restrict__ bk_,
                     const float* __restrict__ bv_,
                     float* __restrict__ Cout)
{
    extern __shared__ char dynsm[];
    const uint32_t smb = smem_u32(dynsm);

    const __half* A_g = IS_O ? g_a : g_xh;
    const __half* W_g = g_wh + (IS_O ? (size_t)3 * HID * HID : 0);

    const int t      = threadIdx.x;
    const int lane   = t & 31;
    const int wid    = t >> 5;
    const int warp_m = wid >> 2;
    const int warp_n = wid & 3;
    const int m0 = blockIdx.y * 128;
    const int n0 = blockIdx.x * 128;

    const int a_row = lane & 15;
    const int a_kb  = (lane >> 4) * 16;
    const int b_row = (lane & 7) + ((lane >> 4) << 3);
    const int b_kb  = ((lane >> 3) & 1) * 16;

    const int lr = t >> 3;
    const int lj = t & 7;

    auto load_chunk = [&](int stage, int k0) {
#pragma unroll
        for (int it = 0; it < 4; it++) {
            const int r = lr + it * 32;
            const size_t aoff = (size_t)(m0 + r) * HID + k0 + lj * 8;
            const size_t woff = (size_t)(n0 + r) * HID + k0 + lj * 8;
            const uint32_t d = smb + stage * G_STAGE + r * 144 + lj * 16;
            cp16(d,          A_g + aoff);
            cp16(d + G_TILE, W_g + woff);
        }
    };

    float acc[4][4][4];
#pragma unroll
    for (int mt = 0; mt < 4; mt++)
#pragma unroll
        for (int nt = 0; nt < 4; nt++)
#pragma unroll
            for (int r = 0; r < 4; r++) acc[mt][nt][r] = 0.f;

    load_chunk(0, 0);   CP_COMMIT();
    load_chunk(1, 64);  CP_COMMIT();

    for (int c = 0; c < 16; c++) {
        if (c + 1 < 16) { CP_WAIT(1); } else { CP_WAIT(0); }
        __syncthreads();
        if (c + 2 < 16) { load_chunk((c + 2) % 3, (c + 2) * 64); CP_COMMIT(); }

        const uint32_t sb = smb + (c % 3) * G_STAGE;
#pragma unroll
        for (int ks = 0; ks < 4; ks++) {
            const int ksb = ks * 32;

            uint32_t af[4][4];
#pragma unroll
            for (int mt = 0; mt < 4; mt++) {
                const uint32_t ro =
                    (uint32_t)((warp_m * 64 + mt * 16 + a_row) * 144 + ksb + a_kb);
                ldsm_x4(af[mt], sb + ro);
            }
            uint32_t bw[2][4];
#pragma unroll
            for (int bt = 0; bt < 2; bt++) {
                const uint32_t ro =
                    (uint32_t)((warp_n * 32 + bt * 16 + b_row) * 144 + ksb + b_kb);
                ldsm_x4(bw[bt], sb + G_TILE + ro);
            }

#pragma unroll
            for (int mt = 0; mt < 4; mt++)
#pragma unroll
                for (int nt = 0; nt < 4; nt++) {
                    const int bt = nt >> 1;
                    const int hf = (nt & 1) * 2;
                    mma_f16(acc[mt][nt], af[mt], bw[bt][hf], bw[bt][hf + 1]);
                }
        }
    }

    // ---- epilogue ----
    const int fr = lane >> 2;
    const int fc = (lane & 3) * 2;
#pragma unroll
    for (int mt = 0; mt < 4; mt++)
#pragma unroll
        for (int nt = 0; nt < 4; nt++) {
            const int n_g = n0 + warp_n * 32 + nt * 8 + fc;
            float2 b2;
            float scl = 1.f;
            int w_idx = 0, n_w = n_g;
            if (!IS_O) {
                w_idx = n_g >> 10;
                n_w   = n_g & 1023;
                const float* bias = (w_idx == 0) ? bq_ : (w_idx == 1) ? bk_ : bv_;
                b2 = *(const float2*)&bias[n_w];
                if (w_idx == 0) scl = QSCALE;
            } else {
                b2 = *(const float2*)&bq_[n_g];
            }
#pragma unroll
            for (int p = 0; p < 2; p++) {
                const int m = m0 + warp_m * 64 + mt * 16 + fr + p * 8;
                const float vx = (acc[mt][nt][p * 2 + 0] + b2.x) * scl;
                const float vy = (acc[mt][nt][p * 2 + 1] + b2.y) * scl;
                if (!IS_O) {
                    const int bb = m >> 11;
                    const int ss = m & (S - 1);
                    const int hh = n_w >> 6;
                    const int dd = n_w & 63;
                    const size_t idx =
                        (((size_t)(bb * NH + hh) * S + ss) << 6) + dd;
                    __half* C = (w_idx == 0) ? g_q : (w_idx == 1) ? g_k : g_v;
                    *(uint32_t*)&C[idx] = pack2f16(vx, vy);
                } else {
                    float2 v; v.x = vx; v.y = vy;
                    *(float2*)&Cout[(size_t)m * HID + n_g] = v;
                }
            }
        }
}

// ---------------------------------------------------------------------------
// Attention: 256 threads, 8 warps, 128 q rows/CTA, 64-key tiles, 3-stage
// cp.async. Softmax: base-2 scores, P via ex2.approx.f16x2, row-sums via a
// "ones column" in the V-tile pad (col 64 = 1.0) accumulated by the PV MMA
// into oacc[8] -> l comes from the SAME fp16 P as the numerator.
// ---------------------------------------------------------------------------
constexpr int A_TILE  = 64 * 144;         // 9216 B
constexpr int A_STAGE = 2 * A_TILE;       // K | V = 18432 B
constexpr int A_SMEM  = 3 * A_STAGE;      // 55296 B -> 2 CTAs/SM

__global__ __launch_bounds__(256, 2)
void attn_mma_kernel()
{
    extern __shared__ char dynsm[];
    const uint32_t smb = smem_u32(dynsm);

    const int t    = threadIdx.x;
    const int lane = t & 31;
    const int w    = t >> 5;
    const int q0   = (gridDim.x - 1 - blockIdx.x) * 128;  // longest first
    const int bh   = blockIdx.y;
    const int bb   = bh >> 4;
    const int hh   = bh & 15;

    const size_t bh_off = (size_t)bh * S * HD;
    const __half* Kh_g = g_k + bh_off;
    const __half* Vh_g = g_v + bh_off;

    // ---- stage Q into stage0 area, pull fragments to registers ----
    {
#pragma unroll
        for (int it = 0; it < 4; it++) {
            const int i = t + it * 256;      // 0..1023 (16B chunks)
            const int r = i >> 3;            // 0..127
            const int j = i & 7;
            const size_t off = bh_off + (size_t)(q0 + r) * HD + j * 8;
            cp16(smb + r * 144 + j * 16, g_q + off);
        }
        CP_COMMIT();
        CP_WAIT(0);
        __syncthreads();
    }

    const int a_row = lane & 15;
    const int a_kb  = (lane >> 4) * 16;
    uint32_t qf[4][4];
#pragma unroll
    for (int ks = 0; ks < 4; ks++) {
        const uint32_t ro = (uint32_t)((w * 16 + a_row) * 144 + ks * 32 + a_kb);
        ldsm_x4(qf[ks], smb + ro);
    }

    // ---- init V-tile pad columns (ones column) once per stage ----
    // cp.async only ever writes bytes 0..127 of each row, so pads persist.
    {
        const uint32_t val = ((t & 3) == 0) ? pack2f16(1.f, 0.f) : 0u;
#pragma unroll
        for (int st = 0; st < 3; st++) {
            const uint32_t addr = smb + st * A_STAGE + A_TILE
                                + (t >> 2) * 144 + 128 + (t & 3) * 4;
            asm volatile("st.shared.b32 [%0], %1;" :: "r"(addr), "r"(val));
        }
    }
    __syncthreads();   // Q consumed + pads visible before tiles load/compute

    const int b_row = (lane & 7) + ((lane >> 4) << 3);
    const int b_kb  = ((lane >> 3) & 1) * 16;

    auto load_tile = [&](int stage, int k0) {
#pragma unroll
        for (int it = 0; it < 2; it++) {
            const int i = t + it * 256;   // 0..511
            const int r = i >> 3;         // 0..63
            const int j = i & 7;
            const size_t off = (size_t)(k0 + r) * HD + j * 8;
            const uint32_t d = smb + stage * A_STAGE + r * 144 + j * 16;
            cp16(d,          Kh_g + off);
            cp16(d + A_TILE, Vh_g + off);
        }
    };

    float m0 = -1e30f, m1 = -1e30f;
    float oacc[9][4];                      // [8] = ones-column sums (l)
#pragma unroll
    for (int nt = 0; nt < 9; nt++)
#pragma unroll
        for (int r = 0; r < 4; r++) oacc[nt][r] = 0.f;

    const int nk = q0 / 64 + 2;
    load_tile(0, 0);  CP_COMMIT();
    load_tile(1, 64); CP_COMMIT();

    for (int ki = 0; ki < nk; ki++) {
        const int k0 = ki * 64;
        if (ki + 1 < nk) { CP_WAIT(1); } else { CP_WAIT(0); }
        __syncthreads();
        if (ki + 2 < nk) { load_tile((ki + 2) % 3, k0 + 128); CP_COMMIT(); }

        const uint32_t sb = smb + (ki % 3) * A_STAGE;

        // ---- S = Q @ K^T (log2-domain scores) ----
        float sacc[8][4];
#pragma unroll
        for (int nt = 0; nt < 8; nt++)
#pragma unroll
            for (int r = 0; r < 4; r++) sacc[nt][r] = 0.f;

#pragma unroll
        for (int ks = 0; ks < 4; ks++) {
            uint32_t kh[4][4];
#pragma unroll
            for (int g = 0; g < 4; g++) {
                const uint32_t ro =
                    (uint32_t)((g * 16 + b_row) * 144 + ks * 32 + b_kb);
                ldsm_x4(kh[g], sb + ro);
            }
#pragma unroll
            for (int nt = 0; nt < 8; nt++) {
                const int g  = nt >> 1;
                const int hf = (nt & 1) * 2;
                mma_f16(sacc[nt], qf[ks], kh[g][hf], kh[g][hf + 1]);
            }
        }

        // ---- causal mask ----
        if (k0 >= q0) {
            const int grow = q0 + w * 16 + (lane >> 2);
#pragma unroll
            for (int nt = 0; nt < 8; nt++) {
                const int gc = k0 + nt * 8 + (lane & 3) * 2;
                if (gc     > grow)     sacc[nt][0] = -1e30f;
                if (gc + 1 > grow)     sacc[nt][1] = -1e30f;
                if (gc     > grow + 8) sacc[nt][2] = -1e30f;
                if (gc + 1 > grow + 8) sacc[nt][3] = -1e30f;
            }
        }

        // ---- online softmax (base-2): max reduce, P = ex2.f16x2 ----
        float mx0 = -1e30f, mx1 = -1e30f;
#pragma unroll
        for (int nt = 0; nt < 8; nt++) {
            mx0 = fmaxf(mx0, fmaxf(sacc[nt][0], sacc[nt][1]));
            mx1 = fmaxf(mx1, fmaxf(sacc[nt][2], sacc[nt][3]));
        }
        mx0 = fmaxf(mx0, __shfl_xor_sync(0xffffffffu, mx0, 1));
        mx0 = fmaxf(mx0, __shfl_xor_sync(0xffffffffu, mx0, 2));
        mx1 = fmaxf(mx1, __shfl_xor_sync(0xffffffffu, mx1, 1));
        mx1 = fmaxf(mx1, __shfl_xor_sync(0xffffffffu, mx1, 2));

        const float mn0 = fmaxf(m0, mx0);
        const float mn1 = fmaxf(m1, mx1);

        uint32_t pp[8][2];
#pragma unroll
        for (int nt = 0; nt < 8; nt++) {
            pp[nt][0] = ex2_f16x2(pack2f16(sacc[nt][0] - mn0,
                                           sacc[nt][1] - mn0));
            pp[nt][1] = ex2_f16x2(pack2f16(sacc[nt][2] - mn1,
                                           sacc[nt][3] - mn1));
        }

        const float sc0 = exp2f(m0 - mn0);
        const float sc1 = exp2f(m1 - mn1);
        m0 = mn0; m1 = mn1;
#pragma unroll
        for (int nt = 0; nt < 9; nt++) {
            oacc[nt][0] *= sc0; oacc[nt][1] *= sc0;
            oacc[nt][2] *= sc1; oacc[nt][3] *= sc1;
        }

        // ---- O += P @ V  (+ ones column -> running row sums in oacc[8]) ----
#pragma unroll
        for (int ks = 0; ks < 4; ks++) {
            uint32_t ph[4];
            ph[0] = pp[2 * ks][0];
            ph[1] = pp[2 * ks][1];
            ph[2] = pp[2 * ks + 1][0];
            ph[3] = pp[2 * ks + 1][1];

            uint32_t vh[4][4];
#pragma unroll
            for (int g = 0; g < 4; g++) {
                const uint32_t ro =
                    (uint32_t)((ks * 16 + a_row) * 144 + g * 32 + a_kb);
                ldsm_x4_t(vh[g], sb + A_TILE + ro);
            }
            uint32_t vo[2];
            ldsm_x2_t(vo, sb + A_TILE
                          + (uint32_t)((ks * 16 + (lane & 15)) * 144 + 128));

#pragma unroll
            for (int nt = 0; nt < 8; nt++) {
                const int g  = nt >> 1;
                const int hf = (nt & 1) * 2;
                mma_f16(oacc[nt], ph, vh[g][hf], vh[g][hf + 1]);
            }
            mma_f16(oacc[8], ph, vo[0], vo[1]);
        }
    }

    // ---- finalize: l from ones-column, write fp16 to g_a [B,S,HID] ----
    const float l0 = __shfl_sync(0xffffffffu, oacc[8][0], lane & ~3);
    const float l1 = __shfl_sync(0xffffffffu, oacc[8][2], lane & ~3);
    const float il0 = 1.f / l0;
    const float il1 = 1.f / l1;
    const int r0 = q0 + w * 16 + (lane >> 2);
#pragma unroll
    for (int nt = 0; nt < 8; nt++) {
        const int d = nt * 8 + (lane & 3) * 2;
        const size_t i0 = ((size_t)bb * S + r0) * HID + hh * 64 + d;
        const size_t i1 = ((size_t)bb * S + r0 + 8) * HID + hh * 64 + d;
        *(uint32_t*)&g_a[i0] = pack2f16(oacc[nt][0] * il0, oacc[nt][1] * il0);
        *(uint32_t*)&g_a[i1] = pack2f16(oacc[nt][2] * il1, oacc[nt][3] * il1);
    }
}

// ---------------------------------------------------------------------------
// Launch
// ---------------------------------------------------------------------------
extern "C" void kernel_launch(void* const* d_in, const int* in_sizes, int n_in,
                              void* d_out, int out_size)
{
    const float* x  = (const float*)d_in[0];
    const float* Wq = (const float*)d_in[1];
    const float* bq = (const float*)d_in[2];
    const float* Wk = (const float*)d_in[3];
    const float* bk = (const float*)d_in[4];
    const float* Wv = (const float*)d_in[5];
    const float* bv = (const float*)d_in[6];
    const float* Wo = (const float*)d_in[7];
    const float* bo = (const float*)d_in[8];
    float* out = (float*)d_out;

    cudaFuncSetAttribute(attn_mma_kernel,
                         cudaFuncAttributeMaxDynamicSharedMemorySize, A_SMEM);
    cudaFuncSetAttribute(gemm_mma_kernel<0>,
                         cudaFuncAttributeMaxDynamicSharedMemorySize, G_SMEM);
    cudaFuncSetAttribute(gemm_mma_kernel<1>,
                         cudaFuncAttributeMaxDynamicSharedMemorySize, G_SMEM);

    cvt_kernel<<<(X_F4 + 4 * W_F4) / 256, 256>>>(x, Wq, Wk, Wv, Wo);

    // fused QKV: n spans 3*1024
    gemm_mma_kernel<0><<<dim3(24, 32), 256, G_SMEM>>>(bq, bk, bv, nullptr);

    attn_mma_kernel<<<dim3(S / 128, B * NH), 256, A_SMEM>>>();

    gemm_mma_kernel<1><<<dim3(8, 32), 256, G_SMEM>>>(bo, nullptr, nullptr, out);
}